// round 4
// baseline (speedup 1.0000x reference)
#include <cuda_runtime.h>
#include <cstdint>

#define BATCH 8
#define NCAND 2535   // 3*13*13 + 3*26*26
#define TOPK 300

// ---------------- scratch (device globals; no allocation) ----------------
__device__ float g_act1[BATCH * 32  * 208 * 208];
__device__ float g_act2[BATCH * 64  * 104 * 104];
__device__ float g_act3[BATCH * 128 * 52  * 52];
__device__ float g_act4[BATCH * 256 * 26  * 26];
__device__ float g_act5[BATCH * 512 * 13  * 13];
__device__ float g_feat1[BATCH * 255 * 13 * 13];
__device__ float g_feat2[BATCH * 255 * 26 * 26];
__device__ float g_cand[BATCH * NCAND * 8]; // ymin,xmin,ymax,xmax,obj,cc,label,score

// ---------------- conv v3: RF couts/thread x 2 vertical pixels ----------
// block = 256 threads = 32 pixel-lanes (16 cols x 2 row-pairs) x 8 warps.
// Each warp handles RF couts (block covers 8*RF couts).
// Weights staged in smem as [c][tap][cout] -> broadcast LDS.128 per 4 couts.
// Input taps: per row one float2 (kx=0,1) + one scalar (kx=2).
// SAME padding for these shapes: pad lo = 0, pad hi = 1 (k=3,s=2) / none (1x1).
template <int KS, int STRIDE, bool LRELU, int RF,
          int CIN, int HIN, int WIN, int HOUT, int WOUT, int COUT>
__global__ void __launch_bounds__(256)
conv3_kernel(const float* __restrict__ in,
             const float* __restrict__ w,
             const float* __restrict__ bias,
             float* __restrict__ out)
{
    constexpr int KK   = KS * KS;
    constexpr int CPB  = 8 * RF;                 // couts per block
    constexpr int CK   = (CIN < 8) ? CIN : 8;    // channel chunk
    constexpr int ROWS = STRIDE + KS;            // 5 for (3,2), 2 for (1,1)
    constexpr int ZC   = (COUT + CPB - 1) / CPB;
    constexpr int HW_IN = HIN * WIN;
    constexpr int P_OUT = HOUT * WOUT;
    constexpr int NG   = RF / 4;                 // float4 groups per tap

    const int tid  = threadIdx.x;
    const int lane = tid & 31;
    const int ty   = tid >> 5;          // warp id: cout group
    const int lx   = lane & 15;         // output col within tile
    const int lyy  = lane >> 4;         // 0/1 row-pair

    const int b   = blockIdx.z / ZC;
    const int czi = blockIdx.z - b * ZC;
    const int co_base = czi * CPB;

    const int ox  = blockIdx.x * 16 + lx;
    const int oy0 = blockIdx.y * 4 + lyy * 2;

    const int ix0 = ox * STRIDE;
    const int iy_base = oy0 * STRIDE;

    const bool pox = ox < WOUT;
    bool pr[ROWS];
    #pragma unroll
    for (int r = 0; r < ROWS; r++) pr[r] = pox && ((iy_base + r) < HIN);
    const bool pc2 = (KS == 3) && ((ix0 + 2) < WIN);

    __shared__ __align__(16) float ws[CK * KK * CPB];

    float acc[2][RF];
    #pragma unroll
    for (int p = 0; p < 2; p++)
        #pragma unroll
        for (int r = 0; r < RF; r++) acc[p][r] = 0.f;

    const float* inb = in + (size_t)b * CIN * HW_IN + iy_base * WIN + ix0;

    for (int c0 = 0; c0 < CIN; c0 += CK) {
        // cooperative weight stage: layout [c][k][co]
        constexpr int TOTAL = CK * KK * CPB;
        for (int idx = tid; idx < TOTAL; idx += 256) {
            int co = idx & (CPB - 1);
            int k  = (idx / CPB) % KK;
            int c  = idx / (CPB * KK);
            int gco = co_base + co;
            ws[idx] = (gco < COUT)
                ? w[((size_t)gco * CIN + (c0 + c)) * KK + k] : 0.f;
        }
        __syncthreads();

        #pragma unroll 2
        for (int c = 0; c < CK; c++) {
            const float* ic = inb + (size_t)(c0 + c) * HW_IN;
            const float* wc = &ws[c * KK * CPB + ty * RF];

            if (KS == 3) {
                // taps: per row float2 (kx0,kx1) + scalar (kx2)
                float iv[ROWS][3];
                #pragma unroll
                for (int r = 0; r < ROWS; r++) {
                    float2 a = pr[r] ? *reinterpret_cast<const float2*>(ic + r * WIN)
                                     : make_float2(0.f, 0.f);
                    float  s = (pr[r] && pc2) ? __ldg(ic + r * WIN + 2) : 0.f;
                    iv[r][0] = a.x; iv[r][1] = a.y; iv[r][2] = s;
                }
                #pragma unroll
                for (int ky = 0; ky < 3; ky++) {
                    #pragma unroll
                    for (int kx = 0; kx < 3; kx++) {
                        const int k = ky * 3 + kx;
                        const float v0 = iv[ky][kx];
                        const float v1 = iv[ky + STRIDE][kx];
                        #pragma unroll
                        for (int g = 0; g < NG; g++) {
                            float4 w4 = *reinterpret_cast<const float4*>(wc + k * CPB + g * 4);
                            acc[0][g*4+0] = fmaf(w4.x, v0, acc[0][g*4+0]);
                            acc[0][g*4+1] = fmaf(w4.y, v0, acc[0][g*4+1]);
                            acc[0][g*4+2] = fmaf(w4.z, v0, acc[0][g*4+2]);
                            acc[0][g*4+3] = fmaf(w4.w, v0, acc[0][g*4+3]);
                            acc[1][g*4+0] = fmaf(w4.x, v1, acc[1][g*4+0]);
                            acc[1][g*4+1] = fmaf(w4.y, v1, acc[1][g*4+1]);
                            acc[1][g*4+2] = fmaf(w4.z, v1, acc[1][g*4+2]);
                            acc[1][g*4+3] = fmaf(w4.w, v1, acc[1][g*4+3]);
                        }
                    }
                }
            } else { // 1x1
                float v0 = pr[0] ? __ldg(ic) : 0.f;
                float v1 = pr[1] ? __ldg(ic + WIN) : 0.f;
                #pragma unroll
                for (int g = 0; g < NG; g++) {
                    float4 w4 = *reinterpret_cast<const float4*>(wc + g * 4);
                    acc[0][g*4+0] = fmaf(w4.x, v0, acc[0][g*4+0]);
                    acc[0][g*4+1] = fmaf(w4.y, v0, acc[0][g*4+1]);
                    acc[0][g*4+2] = fmaf(w4.z, v0, acc[0][g*4+2]);
                    acc[0][g*4+3] = fmaf(w4.w, v0, acc[0][g*4+3]);
                    acc[1][g*4+0] = fmaf(w4.x, v1, acc[1][g*4+0]);
                    acc[1][g*4+1] = fmaf(w4.y, v1, acc[1][g*4+1]);
                    acc[1][g*4+2] = fmaf(w4.z, v1, acc[1][g*4+2]);
                    acc[1][g*4+3] = fmaf(w4.w, v1, acc[1][g*4+3]);
                }
            }
        }
        __syncthreads();
    }

    // store
    if (pox) {
        #pragma unroll
        for (int px = 0; px < 2; px++) {
            int oy = oy0 + px;
            if (oy < HOUT) {
                #pragma unroll
                for (int r = 0; r < RF; r++) {
                    int gco = co_base + ty * RF + r;
                    if (gco < COUT) {
                        float v = acc[px][r] + bias[gco];
                        if (LRELU) v = (v > 0.f) ? v : 0.1f * v;
                        out[((size_t)b * COUT + gco) * P_OUT + oy * WOUT + ox] = v;
                    }
                }
            }
        }
    }
}

// ---------------- decode: feat -> candidate record ----------------
__device__ __forceinline__ float sigmoidf_(float x) { return 1.f / (1.f + expf(-x)); }

__global__ void decode_kernel(const float* __restrict__ feat1,
                              const float* __restrict__ feat2,
                              float* __restrict__ cand)
{
    int idx = blockIdx.x * blockDim.x + threadIdx.x;
    if (idx >= BATCH * NCAND) return;
    int b = idx / NCAND;
    int n = idx - b * NCAND;

    const float A1w[3] = {81.f, 135.f, 344.f}, A1h[3] = {82.f, 169.f, 319.f};
    const float A2w[3] = {10.f, 23.f,  37.f},  A2h[3] = {14.f, 27.f,  58.f};

    const float* fb;
    int H, W, a, yy, xx;
    float aw, ah;
    if (n < 507) {
        H = 13; W = 13;
        a = n / 169; int r = n - a * 169; yy = r / 13; xx = r - yy * 13;
        aw = A1w[a]; ah = A1h[a];
        fb = feat1 + (size_t)b * 255 * 169;
    } else {
        int m = n - 507;
        H = 26; W = 26;
        a = m / 676; int r = m - a * 676; yy = r / 26; xx = r - yy * 26;
        aw = A2w[a]; ah = A2h[a];
        fb = feat2 + (size_t)b * 255 * 676;
    }
    const int HW = H * W;
    const float* base = fb + (size_t)(a * 85) * HW + yy * W + xx;

    float t0 = base[0];
    float t1 = base[HW];
    float t2 = base[2 * HW];
    float t3 = base[3 * HW];
    float t4 = base[4 * HW];

    float bx = (sigmoidf_(t0) + (float)xx) / (float)W;
    float by = (sigmoidf_(t1) + (float)yy) / (float)H;
    float bw = expf(t2) * aw / 416.f;
    float bh = expf(t3) * ah / 416.f;
    float obj = sigmoidf_(t4);

    float ml = base[5 * HW];
    int lab = 0;
    for (int c = 1; c < 80; c++) {
        float v = base[(5 + c) * HW];
        if (v > ml) { ml = v; lab = c; }
    }
    float cc = sigmoidf_(ml);
    float score = obj * cc;
    if (!(score >= 0.1f)) score = 0.f;

    float* o = cand + (size_t)idx * 8;
    o[0] = (by - bh * 0.5f) * 416.f;
    o[1] = (bx - bw * 0.5f) * 416.f;
    o[2] = (by + bh * 0.5f) * 416.f;
    o[3] = (bx + bw * 0.5f) * 416.f;
    o[4] = obj;
    o[5] = cc;
    o[6] = (float)lab;
    o[7] = score;
}

// ---------------- per-image top-k + greedy NMS ----------------
__device__ __forceinline__ void argmax2(float& v, int& i, float v2, int i2)
{
    if (v2 > v || (v2 == v && i2 < i)) { v = v2; i = i2; }
}

__global__ void nms_kernel(const float* __restrict__ cand, float* __restrict__ out)
{
    const int b = blockIdx.x;
    const int tid = threadIdx.x; // 512 threads
    const int lane = tid & 31;
    const int wid  = tid >> 5;   // 16 warps

    __shared__ float s[NCAND];
    __shared__ int   sel[TOPK];
    __shared__ float wv[16];
    __shared__ int   wi[16];

    const float* cb = cand + (size_t)b * NCAND * 8;
    for (int i = tid; i < NCAND; i += 512) s[i] = cb[i * 8 + 7];
    __syncthreads();

    // top-300: 300 rounds of block argmax (value desc, index asc tiebreak)
    for (int r = 0; r < TOPK; r++) {
        float bv = -1.f; int bi = NCAND + 1;
        for (int i = tid; i < NCAND; i += 512)
            argmax2(bv, bi, s[i], i);
        #pragma unroll
        for (int o = 16; o > 0; o >>= 1) {
            float v2 = __shfl_down_sync(0xffffffffu, bv, o);
            int   i2 = __shfl_down_sync(0xffffffffu, bi, o);
            argmax2(bv, bi, v2, i2);
        }
        if (lane == 0) { wv[wid] = bv; wi[wid] = bi; }
        __syncthreads();
        if (wid == 0) {
            float v = (lane < 16) ? wv[lane] : -3.f;
            int   i = (lane < 16) ? wi[lane] : NCAND + 2;
            #pragma unroll
            for (int o = 8; o > 0; o >>= 1) {
                float v2 = __shfl_down_sync(0xffffffffu, v, o);
                int   i2 = __shfl_down_sync(0xffffffffu, i, o);
                argmax2(v, i, v2, i2);
            }
            if (lane == 0) { sel[r] = i; s[i] = -2.f; }
        }
        __syncthreads();
    }

    // load selected boxes
    __shared__ float y0s[TOPK], x0s[TOPK], y1s[TOPK], x1s[TOPK], areas[TOPK];
    __shared__ int labs[TOPK];
    __shared__ unsigned char keep[TOPK];
    if (tid < TOPK) {
        int ii = sel[tid];
        float y0 = cb[ii * 8 + 0], x0 = cb[ii * 8 + 1];
        float y1 = cb[ii * 8 + 2], x1 = cb[ii * 8 + 3];
        y0s[tid] = y0; x0s[tid] = x0; y1s[tid] = y1; x1s[tid] = x1;
        areas[tid] = (y1 - y0) * (x1 - x0);
        labs[tid] = (int)cb[ii * 8 + 6];
        keep[tid] = (cb[ii * 8 + 7] > 0.f) ? 1 : 0;
    }
    __syncthreads();

    // sequential greedy suppression (matches the fori_loop semantics)
    for (int j = 0; j < TOPK - 1; j++) {
        if (tid > j && tid < TOPK && keep[j] && keep[tid] && labs[tid] == labs[j]) {
            float ty0 = fmaxf(y0s[tid], y0s[j]);
            float tx0 = fmaxf(x0s[tid], x0s[j]);
            float ty1 = fminf(y1s[tid], y1s[j]);
            float tx1 = fminf(x1s[tid], x1s[j]);
            float ih = fmaxf(ty1 - ty0, 0.f);
            float iw = fmaxf(tx1 - tx0, 0.f);
            float inter = ih * iw;
            float iou = inter / (areas[tid] + areas[j] - inter + 1e-9f);
            if (iou > 0.5f) keep[tid] = 0;
        }
        __syncthreads();
    }

    if (tid < TOPK) {
        float* o = out + ((size_t)b * TOPK + tid) * 7;
        if (keep[tid]) {
            int ii = sel[tid];
            o[0] = y0s[tid]; o[1] = x0s[tid]; o[2] = y1s[tid]; o[3] = x1s[tid];
            o[4] = cb[ii * 8 + 4];
            o[5] = cb[ii * 8 + 5];
            o[6] = (float)labs[tid];
        } else {
            #pragma unroll
            for (int k = 0; k < 7; k++) o[k] = 0.f;
        }
    }
}

// ---------------- launch ----------------
static inline int ceil_div(int a, int b) { return (a + b - 1) / b; }

extern "C" void kernel_launch(void* const* d_in, const int* in_sizes, int n_in,
                              void* d_out, int out_size)
{
    (void)in_sizes; (void)n_in; (void)out_size;
    const float* images = (const float*)d_in[0];
    const float* w1 = (const float*)d_in[1];  const float* b1 = (const float*)d_in[2];
    const float* w2 = (const float*)d_in[3];  const float* b2 = (const float*)d_in[4];
    const float* w3 = (const float*)d_in[5];  const float* b3 = (const float*)d_in[6];
    const float* w4 = (const float*)d_in[7];  const float* b4 = (const float*)d_in[8];
    const float* w5 = (const float*)d_in[9];  const float* b5 = (const float*)d_in[10];
    const float* wh1 = (const float*)d_in[11]; const float* bh1 = (const float*)d_in[12];
    const float* wh2 = (const float*)d_in[13]; const float* bh2 = (const float*)d_in[14];
    float* out = (float*)d_out;

    static float *act1 = nullptr, *act2, *act3, *act4, *act5, *feat1, *feat2, *cand;
    if (!act1) {
        cudaGetSymbolAddress((void**)&act1, g_act1);
        cudaGetSymbolAddress((void**)&act2, g_act2);
        cudaGetSymbolAddress((void**)&act3, g_act3);
        cudaGetSymbolAddress((void**)&act4, g_act4);
        cudaGetSymbolAddress((void**)&act5, g_act5);
        cudaGetSymbolAddress((void**)&feat1, g_feat1);
        cudaGetSymbolAddress((void**)&feat2, g_feat2);
        cudaGetSymbolAddress((void**)&cand, g_cand);
    }

    // L1: 3 -> 32, 416 -> 208  (RF=4, one cout tile of 32)
    conv3_kernel<3, 2, true, 4, 3, 416, 416, 208, 208, 32>
        <<<dim3(ceil_div(208,16), ceil_div(208,4), BATCH * 1), 256>>>(images, w1, b1, act1);
    // L2: 32 -> 64, 208 -> 104 (RF=8, CPB=64, ZC=1)
    conv3_kernel<3, 2, true, 8, 32, 208, 208, 104, 104, 64>
        <<<dim3(ceil_div(104,16), ceil_div(104,4), BATCH * 1), 256>>>(act1, w2, b2, act2);
    // L3: 64 -> 128, 104 -> 52 (ZC=2)
    conv3_kernel<3, 2, true, 8, 64, 104, 104, 52, 52, 128>
        <<<dim3(ceil_div(52,16), ceil_div(52,4), BATCH * 2), 256>>>(act2, w3, b3, act3);
    // L4: 128 -> 256, 52 -> 26 (ZC=4)
    conv3_kernel<3, 2, true, 8, 128, 52, 52, 26, 26, 256>
        <<<dim3(ceil_div(26,16), ceil_div(26,4), BATCH * 4), 256>>>(act3, w4, b4, act4);
    // head2: 256 -> 255 @ 26x26 (ZC=4)
    conv3_kernel<1, 1, false, 8, 256, 26, 26, 26, 26, 255>
        <<<dim3(ceil_div(26,16), ceil_div(26,4), BATCH * 4), 256>>>(act4, wh2, bh2, feat2);
    // L5: 256 -> 512, 26 -> 13 (ZC=8)
    conv3_kernel<3, 2, true, 8, 256, 26, 26, 13, 13, 512>
        <<<dim3(ceil_div(13,16), ceil_div(13,4), BATCH * 8), 256>>>(act4, w5, b5, act5);
    // head1: 512 -> 255 @ 13x13 (ZC=4)
    conv3_kernel<1, 1, false, 8, 512, 13, 13, 13, 13, 255>
        <<<dim3(ceil_div(13,16), ceil_div(13,4), BATCH * 4), 256>>>(act5, wh1, bh1, feat1);
    // decode
    decode_kernel<<<ceil_div(BATCH * NCAND, 256), 256>>>(feat1, feat2, cand);
    // nms + output
    nms_kernel<<<BATCH, 512>>>(cand, out);
}

// round 5
// speedup vs baseline: 1.5046x; 1.5046x over previous
#include <cuda_runtime.h>
#include <cstdint>

#define BATCH 8
#define NCAND 2535   // 3*13*13 + 3*26*26
#define TOPK 300

typedef unsigned long long u64;

__device__ __forceinline__ u64 pack2(float x, float y) {
    u64 r;
    asm("mov.b64 %0, {%1, %2};" : "=l"(r)
        : "r"(__float_as_uint(x)), "r"(__float_as_uint(y)));
    return r;
}
__device__ __forceinline__ void unpack2(u64 v, float& x, float& y) {
    unsigned a, b;
    asm("mov.b64 {%0, %1}, %2;" : "=r"(a), "=r"(b) : "l"(v));
    x = __uint_as_float(a); y = __uint_as_float(b);
}
__device__ __forceinline__ u64 fma2(u64 a, u64 b, u64 c) {
    u64 d;
    asm("fma.rn.f32x2 %0, %1, %2, %3;" : "=l"(d) : "l"(a), "l"(b), "l"(c));
    return d;
}

// ---------------- scratch (device globals; no allocation) ----------------
// activations in [C][BATCH*H*W] layout
__device__ float g_act1[32  * BATCH * 208 * 208];
__device__ float g_act2[64  * BATCH * 104 * 104];
__device__ float g_act3[128 * BATCH * 52  * 52];
__device__ float g_act4[256 * BATCH * 26  * 26];
__device__ float g_act5[512 * BATCH * 13  * 13];
__device__ float g_feat1[255 * BATCH * 13 * 13];
__device__ float g_feat2[255 * BATCH * 26 * 26];
__device__ float g_col[25000000];                 // im2col scratch (max 288*86528)
__device__ float g_cand[BATCH * NCAND * 8];

// ---------------- im2col: in -> col[K9][BATCH*P] ----------------
// k = c*9 + ky*3 + kx ; n = b*P + oy*W + ox ; iy=2oy+ky, ix=2ox+kx (pad hi 1)
template <int CIN, int HIN, int WIN, int HOUT, int WOUT, bool NCHW>
__global__ void im2col_kernel(const float* __restrict__ in, float* __restrict__ col)
{
    constexpr int P = HOUT * WOUT;
    constexpr int NN = BATCH * P;
    constexpr int HWIN = HIN * WIN;
    const int k = blockIdx.y;
    const int n = blockIdx.x * 256 + threadIdx.x;
    if (n >= NN) return;
    const int c  = k / 9;
    const int t  = k - 9 * c;
    const int ky = t / 3;
    const int kx = t - 3 * ky;
    const int b  = n / P;
    const int p  = n - b * P;
    const int oy = p / WOUT;
    const int ox = p - oy * WOUT;
    const int iy = 2 * oy + ky;
    const int ix = 2 * ox + kx;
    float v = 0.f;
    if (iy < HIN && ix < WIN) {
        v = NCHW ? in[((size_t)(b * CIN + c) * HIN + iy) * WIN + ix]
                 : in[(size_t)(c * BATCH + b) * HWIN + iy * WIN + ix];
    }
    col[(size_t)k * NN + n] = v;
}

// ---------------- SGEMM (f32x2): C[M][N] = A[M][K] * B[K][N] + bias -------
// BM x BN tile, BK=16, 256 threads, TM x 8 micro-tile per thread.
template <int M, int N, int K, int BM, int BN, int TM, bool LRELU>
__global__ void __launch_bounds__(256)
gemm_kernel(const float* __restrict__ A, const float* __restrict__ B,
            const float* __restrict__ bias, float* __restrict__ C)
{
    constexpr int BK = 16;
    constexpr int TX = BN / 8;      // 16
    constexpr int TY = BM / TM;     // 16
    static_assert(TX * TY == 256, "thread count");
    constexpr int NB4 = BN / 4;     // float4 cols per Bs row

    __shared__ __align__(16) float  As[BK][BM + 4];
    __shared__ __align__(16) float4 Bs4[BK][NB4];

    const int tid = threadIdx.x;
    const int tx  = tid % TX;
    const int ty  = tid / TX;
    const int m0  = blockIdx.y * BM;
    const int n0  = blockIdx.x * BN;

    u64 acc[TM][4];
    #pragma unroll
    for (int i = 0; i < TM; i++)
        #pragma unroll
        for (int j = 0; j < 4; j++) acc[i][j] = pack2(0.f, 0.f);

    for (int kt = 0; kt < K; kt += BK) {
        // stage A tile transposed: As[kk][m]
        #pragma unroll
        for (int i = tid; i < BM * BK; i += 256) {
            int m  = i >> 4;
            int kk = i & 15;
            float v = 0.f;
            bool ok = true;
            if (M % BM != 0) ok = (m0 + m) < M;
            if (K % BK != 0) ok = ok && (kt + kk) < K;
            if (ok) v = A[(size_t)(m0 + m) * K + kt + kk];
            As[kk][m] = v;
        }
        // stage B tile: Bs4[kk][n4]
        #pragma unroll
        for (int i = tid; i < BK * NB4; i += 256) {
            int kk = i / NB4;
            int n4 = i - kk * NB4;
            int gn = n0 + n4 * 4;
            float4 v = make_float4(0.f, 0.f, 0.f, 0.f);
            bool ok = true;
            if (K % BK != 0) ok = (kt + kk) < K;
            if (N % BN != 0) ok = ok && (gn < N);   // N % 4 == 0 always
            if (ok) v = *reinterpret_cast<const float4*>(&B[(size_t)(kt + kk) * N + gn]);
            Bs4[kk][n4] = v;
        }
        __syncthreads();

        #pragma unroll
        for (int kk = 0; kk < BK; kk++) {
            float4 bfa = Bs4[kk][tx];             // cols n0 + tx*4 ..
            float4 bfb = Bs4[kk][NB4 / 2 + tx];   // cols n0 + BN/2 + tx*4 ..
            u64 b01 = pack2(bfa.x, bfa.y);
            u64 b23 = pack2(bfa.z, bfa.w);
            u64 b45 = pack2(bfb.x, bfb.y);
            u64 b67 = pack2(bfb.z, bfb.w);
            float av[TM];
            if (TM == 4) {
                float4 a4 = *reinterpret_cast<const float4*>(&As[kk][ty * 4]);
                av[0] = a4.x; av[1] = a4.y; av[2] = a4.z; av[3] = a4.w;
            } else { // TM == 2
                float2 a2 = *reinterpret_cast<const float2*>(&As[kk][ty * 2]);
                av[0] = a2.x; av[1] = a2.y;
            }
            #pragma unroll
            for (int i = 0; i < TM; i++) {
                u64 a2p = pack2(av[i], av[i]);
                acc[i][0] = fma2(a2p, b01, acc[i][0]);
                acc[i][1] = fma2(a2p, b23, acc[i][1]);
                acc[i][2] = fma2(a2p, b45, acc[i][2]);
                acc[i][3] = fma2(a2p, b67, acc[i][3]);
            }
        }
        __syncthreads();
    }

    // epilogue
    #pragma unroll
    for (int i = 0; i < TM; i++) {
        int m = m0 + ty * TM + i;
        if (M % BM != 0 && m >= M) continue;
        float bb = bias[m];
        float x0, x1, x2, x3;

        int gn = n0 + tx * 4;
        if (N % BN == 0 || gn < N) {
            unpack2(acc[i][0], x0, x1);
            unpack2(acc[i][1], x2, x3);
            x0 += bb; x1 += bb; x2 += bb; x3 += bb;
            if (LRELU) {
                x0 = x0 > 0.f ? x0 : 0.1f * x0;
                x1 = x1 > 0.f ? x1 : 0.1f * x1;
                x2 = x2 > 0.f ? x2 : 0.1f * x2;
                x3 = x3 > 0.f ? x3 : 0.1f * x3;
            }
            *reinterpret_cast<float4*>(&C[(size_t)m * N + gn]) = make_float4(x0, x1, x2, x3);
        }
        int gn2 = n0 + BN / 2 + tx * 4;
        if (N % BN == 0 || gn2 < N) {
            unpack2(acc[i][2], x0, x1);
            unpack2(acc[i][3], x2, x3);
            x0 += bb; x1 += bb; x2 += bb; x3 += bb;
            if (LRELU) {
                x0 = x0 > 0.f ? x0 : 0.1f * x0;
                x1 = x1 > 0.f ? x1 : 0.1f * x1;
                x2 = x2 > 0.f ? x2 : 0.1f * x2;
                x3 = x3 > 0.f ? x3 : 0.1f * x3;
            }
            *reinterpret_cast<float4*>(&C[(size_t)m * N + gn2]) = make_float4(x0, x1, x2, x3);
        }
    }
}

// ---------------- decode: feat (CNHW) -> candidate record ----------------
__device__ __forceinline__ float sigmoidf_(float x) { return 1.f / (1.f + expf(-x)); }

__global__ void decode_kernel(const float* __restrict__ feat1,
                              const float* __restrict__ feat2,
                              float* __restrict__ cand)
{
    int idx = blockIdx.x * blockDim.x + threadIdx.x;
    if (idx >= BATCH * NCAND) return;
    int b = idx / NCAND;
    int n = idx - b * NCAND;

    const float A1w[3] = {81.f, 135.f, 344.f}, A1h[3] = {82.f, 169.f, 319.f};
    const float A2w[3] = {10.f, 23.f,  37.f},  A2h[3] = {14.f, 27.f,  58.f};

    const float* base;
    int H, W, a, yy, xx;
    size_t estr;
    float aw, ah;
    if (n < 507) {
        H = 13; W = 13;
        a = n / 169; int r = n - a * 169; yy = r / 13; xx = r - yy * 13;
        aw = A1w[a]; ah = A1h[a];
        estr = (size_t)BATCH * 169;
        base = feat1 + (size_t)(a * 85) * estr + b * 169 + yy * 13 + xx;
    } else {
        int m = n - 507;
        H = 26; W = 26;
        a = m / 676; int r = m - a * 676; yy = r / 26; xx = r - yy * 26;
        aw = A2w[a]; ah = A2h[a];
        estr = (size_t)BATCH * 676;
        base = feat2 + (size_t)(a * 85) * estr + b * 676 + yy * 26 + xx;
    }

    float t0 = base[0];
    float t1 = base[estr];
    float t2 = base[2 * estr];
    float t3 = base[3 * estr];
    float t4 = base[4 * estr];

    float bx = (sigmoidf_(t0) + (float)xx) / (float)W;
    float by = (sigmoidf_(t1) + (float)yy) / (float)H;
    float bw = expf(t2) * aw / 416.f;
    float bh = expf(t3) * ah / 416.f;
    float obj = sigmoidf_(t4);

    float ml = base[5 * estr];
    int lab = 0;
    for (int c = 1; c < 80; c++) {
        float v = base[(5 + c) * estr];
        if (v > ml) { ml = v; lab = c; }
    }
    float cc = sigmoidf_(ml);
    float score = obj * cc;
    if (!(score >= 0.1f)) score = 0.f;

    float* o = cand + (size_t)idx * 8;
    o[0] = (by - bh * 0.5f) * 416.f;
    o[1] = (bx - bw * 0.5f) * 416.f;
    o[2] = (by + bh * 0.5f) * 416.f;
    o[3] = (bx + bw * 0.5f) * 416.f;
    o[4] = obj;
    o[5] = cc;
    o[6] = (float)lab;
    o[7] = score;
}

// ---------------- per-image top-k + greedy NMS ----------------
__device__ __forceinline__ void argmax2(float& v, int& i, float v2, int i2)
{
    if (v2 > v || (v2 == v && i2 < i)) { v = v2; i = i2; }
}

__global__ void nms_kernel(const float* __restrict__ cand, float* __restrict__ out)
{
    const int b = blockIdx.x;
    const int tid = threadIdx.x; // 512 threads
    const int lane = tid & 31;
    const int wid  = tid >> 5;   // 16 warps

    __shared__ float s[NCAND];
    __shared__ int   sel[TOPK];
    __shared__ float wv[16];
    __shared__ int   wi[16];

    const float* cb = cand + (size_t)b * NCAND * 8;
    for (int i = tid; i < NCAND; i += 512) s[i] = cb[i * 8 + 7];
    __syncthreads();

    for (int r = 0; r < TOPK; r++) {
        float bv = -1.f; int bi = NCAND + 1;
        for (int i = tid; i < NCAND; i += 512)
            argmax2(bv, bi, s[i], i);
        #pragma unroll
        for (int o = 16; o > 0; o >>= 1) {
            float v2 = __shfl_down_sync(0xffffffffu, bv, o);
            int   i2 = __shfl_down_sync(0xffffffffu, bi, o);
            argmax2(bv, bi, v2, i2);
        }
        if (lane == 0) { wv[wid] = bv; wi[wid] = bi; }
        __syncthreads();
        if (wid == 0) {
            float v = (lane < 16) ? wv[lane] : -3.f;
            int   i = (lane < 16) ? wi[lane] : NCAND + 2;
            #pragma unroll
            for (int o = 8; o > 0; o >>= 1) {
                float v2 = __shfl_down_sync(0xffffffffu, v, o);
                int   i2 = __shfl_down_sync(0xffffffffu, i, o);
                argmax2(v, i, v2, i2);
            }
            if (lane == 0) { sel[r] = i; s[i] = -2.f; }
        }
        __syncthreads();
    }

    __shared__ float y0s[TOPK], x0s[TOPK], y1s[TOPK], x1s[TOPK], areas[TOPK];
    __shared__ int labs[TOPK];
    __shared__ unsigned char keep[TOPK];
    if (tid < TOPK) {
        int ii = sel[tid];
        float y0 = cb[ii * 8 + 0], x0 = cb[ii * 8 + 1];
        float y1 = cb[ii * 8 + 2], x1 = cb[ii * 8 + 3];
        y0s[tid] = y0; x0s[tid] = x0; y1s[tid] = y1; x1s[tid] = x1;
        areas[tid] = (y1 - y0) * (x1 - x0);
        labs[tid] = (int)cb[ii * 8 + 6];
        keep[tid] = (cb[ii * 8 + 7] > 0.f) ? 1 : 0;
    }
    __syncthreads();

    for (int j = 0; j < TOPK - 1; j++) {
        if (tid > j && tid < TOPK && keep[j] && keep[tid] && labs[tid] == labs[j]) {
            float ty0 = fmaxf(y0s[tid], y0s[j]);
            float tx0 = fmaxf(x0s[tid], x0s[j]);
            float ty1 = fminf(y1s[tid], y1s[j]);
            float tx1 = fminf(x1s[tid], x1s[j]);
            float ih = fmaxf(ty1 - ty0, 0.f);
            float iw = fmaxf(tx1 - tx0, 0.f);
            float inter = ih * iw;
            float iou = inter / (areas[tid] + areas[j] - inter + 1e-9f);
            if (iou > 0.5f) keep[tid] = 0;
        }
        __syncthreads();
    }

    if (tid < TOPK) {
        float* o = out + ((size_t)b * TOPK + tid) * 7;
        if (keep[tid]) {
            int ii = sel[tid];
            o[0] = y0s[tid]; o[1] = x0s[tid]; o[2] = y1s[tid]; o[3] = x1s[tid];
            o[4] = cb[ii * 8 + 4];
            o[5] = cb[ii * 8 + 5];
            o[6] = (float)labs[tid];
        } else {
            #pragma unroll
            for (int k = 0; k < 7; k++) o[k] = 0.f;
        }
    }
}

// ---------------- launch ----------------
static inline int ceil_div(int a, int b) { return (a + b - 1) / b; }

extern "C" void kernel_launch(void* const* d_in, const int* in_sizes, int n_in,
                              void* d_out, int out_size)
{
    (void)in_sizes; (void)n_in; (void)out_size;
    const float* images = (const float*)d_in[0];
    const float* w1 = (const float*)d_in[1];  const float* b1 = (const float*)d_in[2];
    const float* w2 = (const float*)d_in[3];  const float* b2 = (const float*)d_in[4];
    const float* w3 = (const float*)d_in[5];  const float* b3 = (const float*)d_in[6];
    const float* w4 = (const float*)d_in[7];  const float* b4 = (const float*)d_in[8];
    const float* w5 = (const float*)d_in[9];  const float* b5 = (const float*)d_in[10];
    const float* wh1 = (const float*)d_in[11]; const float* bh1 = (const float*)d_in[12];
    const float* wh2 = (const float*)d_in[13]; const float* bh2 = (const float*)d_in[14];
    float* out = (float*)d_out;

    static float *act1 = nullptr, *act2, *act3, *act4, *act5, *feat1, *feat2, *col, *cand;
    if (!act1) {
        cudaGetSymbolAddress((void**)&act1, g_act1);
        cudaGetSymbolAddress((void**)&act2, g_act2);
        cudaGetSymbolAddress((void**)&act3, g_act3);
        cudaGetSymbolAddress((void**)&act4, g_act4);
        cudaGetSymbolAddress((void**)&act5, g_act5);
        cudaGetSymbolAddress((void**)&feat1, g_feat1);
        cudaGetSymbolAddress((void**)&feat2, g_feat2);
        cudaGetSymbolAddress((void**)&col,  g_col);
        cudaGetSymbolAddress((void**)&cand, g_cand);
    }

    // --- L1: 3->32, 416->208  (N = 8*208*208 = 346112, K = 27)
    im2col_kernel<3, 416, 416, 208, 208, true>
        <<<dim3(ceil_div(346112, 256), 27), 256>>>(images, col);
    gemm_kernel<32, 346112, 27, 32, 128, 2, true>
        <<<dim3(346112 / 128, 1), 256>>>(w1, col, b1, act1);

    // --- L2: 32->64, 208->104 (N = 86528, K = 288)
    im2col_kernel<32, 208, 208, 104, 104, false>
        <<<dim3(ceil_div(86528, 256), 288), 256>>>(act1, col);
    gemm_kernel<64, 86528, 288, 64, 128, 4, true>
        <<<dim3(86528 / 128, 1), 256>>>(w2, col, b2, act2);

    // --- L3: 64->128, 104->52 (N = 21632, K = 576)
    im2col_kernel<64, 104, 104, 52, 52, false>
        <<<dim3(ceil_div(21632, 256), 576), 256>>>(act2, col);
    gemm_kernel<128, 21632, 576, 64, 128, 4, true>
        <<<dim3(21632 / 128, 2), 256>>>(w3, col, b3, act3);

    // --- L4: 128->256, 52->26 (N = 5408, K = 1152)
    im2col_kernel<128, 52, 52, 26, 26, false>
        <<<dim3(ceil_div(5408, 256), 1152), 256>>>(act3, col);
    gemm_kernel<256, 5408, 1152, 64, 128, 4, true>
        <<<dim3(ceil_div(5408, 128), 4), 256>>>(w4, col, b4, act4);

    // --- head2: 255 x 5408, K = 256 (pure GEMM on act4)
    gemm_kernel<255, 5408, 256, 64, 128, 4, false>
        <<<dim3(ceil_div(5408, 128), 4), 256>>>(wh2, act4, bh2, feat2);

    // --- L5: 256->512, 26->13 (N = 1352, K = 2304)
    im2col_kernel<256, 26, 26, 13, 13, false>
        <<<dim3(ceil_div(1352, 256), 2304), 256>>>(act4, col);
    gemm_kernel<512, 1352, 2304, 64, 128, 4, true>
        <<<dim3(ceil_div(1352, 128), 8), 256>>>(w5, col, b5, act5);

    // --- head1: 255 x 1352, K = 512 (pure GEMM on act5)
    gemm_kernel<255, 1352, 512, 64, 128, 4, false>
        <<<dim3(ceil_div(1352, 128), 4), 256>>>(wh1, act5, bh1, feat1);

    // --- decode + nms
    decode_kernel<<<ceil_div(BATCH * NCAND, 256), 256>>>(feat1, feat2, cand);
    nms_kernel<<<BATCH, 512>>>(cand, out);
}

// round 6
// speedup vs baseline: 1.6982x; 1.1287x over previous
#include <cuda_runtime.h>
#include <cstdint>

#define BATCH 8
#define NCAND 2535   // 3*13*13 + 3*26*26
#define TOPK 300

typedef unsigned long long u64;

__device__ __forceinline__ u64 pack2(float x, float y) {
    u64 r;
    asm("mov.b64 %0, {%1, %2};" : "=l"(r)
        : "r"(__float_as_uint(x)), "r"(__float_as_uint(y)));
    return r;
}
__device__ __forceinline__ void unpack2(u64 v, float& x, float& y) {
    unsigned a, b;
    asm("mov.b64 {%0, %1}, %2;" : "=r"(a), "=r"(b) : "l"(v));
    x = __uint_as_float(a); y = __uint_as_float(b);
}
__device__ __forceinline__ u64 fma2(u64 a, u64 b, u64 c) {
    u64 d;
    asm("fma.rn.f32x2 %0, %1, %2, %3;" : "=l"(d) : "l"(a), "l"(b), "l"(c));
    return d;
}

// ---------------- scratch (device globals; no allocation) ----------------
__device__ float g_act1[32  * BATCH * 208 * 208];
__device__ float g_act2[64  * BATCH * 104 * 104];
__device__ float g_act3[128 * BATCH * 52  * 52];
__device__ float g_act4[256 * BATCH * 26  * 26];
__device__ float g_act5[512 * BATCH * 13  * 13];
__device__ float g_feat1[255 * BATCH * 13 * 13];
__device__ float g_feat2[255 * BATCH * 26 * 26];
__device__ float g_col[25000000];   // im2col scratch + split-K partials @ +10M
__device__ float g_cand[BATCH * NCAND * 8];

#define PARTIAL_OFF 10000000

// ---------------- im2col: in -> col[K9][BATCH*P] ----------------
template <int CIN, int HIN, int WIN, int HOUT, int WOUT, bool NCHW>
__global__ void im2col_kernel(const float* __restrict__ in, float* __restrict__ col)
{
    constexpr int P = HOUT * WOUT;
    constexpr int NN = BATCH * P;
    constexpr int HWIN = HIN * WIN;
    const int k = blockIdx.y;
    const int n = blockIdx.x * 256 + threadIdx.x;
    if (n >= NN) return;
    const int c  = k / 9;
    const int t  = k - 9 * c;
    const int ky = t / 3;
    const int kx = t - 3 * ky;
    const int b  = n / P;
    const int p  = n - b * P;
    const int oy = p / WOUT;
    const int ox = p - oy * WOUT;
    const int iy = 2 * oy + ky;
    const int ix = 2 * ox + kx;
    float v = 0.f;
    if (iy < HIN && ix < WIN) {
        v = NCHW ? in[((size_t)(b * CIN + c) * HIN + iy) * WIN + ix]
                 : in[(size_t)(c * BATCH + b) * HWIN + iy * WIN + ix];
    }
    col[(size_t)k * NN + n] = v;
}

// ---------------- small-M GEMM for L1 (K=27, M=32) ----------------
template <int M, int N, int K, int BM, int BN, int TM, bool LRELU>
__global__ void __launch_bounds__(256)
gemm_kernel(const float* __restrict__ A, const float* __restrict__ B,
            const float* __restrict__ bias, float* __restrict__ C)
{
    constexpr int BK = 16;
    constexpr int TX = BN / 8;
    constexpr int TY = BM / TM;
    static_assert(TX * TY == 256, "thread count");
    constexpr int NB4 = BN / 4;

    __shared__ __align__(16) float  As[BK][BM + 4];
    __shared__ __align__(16) float4 Bs4[BK][NB4];

    const int tid = threadIdx.x;
    const int tx  = tid % TX;
    const int ty  = tid / TX;
    const int m0  = blockIdx.y * BM;
    const int n0  = blockIdx.x * BN;

    u64 acc[TM][4];
    #pragma unroll
    for (int i = 0; i < TM; i++)
        #pragma unroll
        for (int j = 0; j < 4; j++) acc[i][j] = pack2(0.f, 0.f);

    for (int kt = 0; kt < K; kt += BK) {
        #pragma unroll
        for (int i = tid; i < BM * BK; i += 256) {
            int m  = i >> 4;
            int kk = i & 15;
            float v = 0.f;
            bool ok = true;
            if (M % BM != 0) ok = (m0 + m) < M;
            if (K % BK != 0) ok = ok && (kt + kk) < K;
            if (ok) v = A[(size_t)(m0 + m) * K + kt + kk];
            As[kk][m] = v;
        }
        #pragma unroll
        for (int i = tid; i < BK * NB4; i += 256) {
            int kk = i / NB4;
            int n4 = i - kk * NB4;
            int gn = n0 + n4 * 4;
            float4 v = make_float4(0.f, 0.f, 0.f, 0.f);
            bool ok = true;
            if (K % BK != 0) ok = (kt + kk) < K;
            if (N % BN != 0) ok = ok && (gn < N);
            if (ok) v = *reinterpret_cast<const float4*>(&B[(size_t)(kt + kk) * N + gn]);
            Bs4[kk][n4] = v;
        }
        __syncthreads();

        #pragma unroll
        for (int kk = 0; kk < BK; kk++) {
            float4 bfa = Bs4[kk][tx];
            float4 bfb = Bs4[kk][NB4 / 2 + tx];
            u64 b01 = pack2(bfa.x, bfa.y);
            u64 b23 = pack2(bfa.z, bfa.w);
            u64 b45 = pack2(bfb.x, bfb.y);
            u64 b67 = pack2(bfb.z, bfb.w);
            float av[TM];
            float2 a2 = *reinterpret_cast<const float2*>(&As[kk][ty * 2]);
            av[0] = a2.x; av[1] = a2.y;
            #pragma unroll
            for (int i = 0; i < TM; i++) {
                u64 a2p = pack2(av[i], av[i]);
                acc[i][0] = fma2(a2p, b01, acc[i][0]);
                acc[i][1] = fma2(a2p, b23, acc[i][1]);
                acc[i][2] = fma2(a2p, b45, acc[i][2]);
                acc[i][3] = fma2(a2p, b67, acc[i][3]);
            }
        }
        __syncthreads();
    }

    #pragma unroll
    for (int i = 0; i < TM; i++) {
        int m = m0 + ty * TM + i;
        if (M % BM != 0 && m >= M) continue;
        float bb = bias[m];
        float x0, x1, x2, x3;
        int gn = n0 + tx * 4;
        if (N % BN == 0 || gn < N) {
            unpack2(acc[i][0], x0, x1);
            unpack2(acc[i][1], x2, x3);
            x0 += bb; x1 += bb; x2 += bb; x3 += bb;
            if (LRELU) {
                x0 = x0 > 0.f ? x0 : 0.1f * x0;
                x1 = x1 > 0.f ? x1 : 0.1f * x1;
                x2 = x2 > 0.f ? x2 : 0.1f * x2;
                x3 = x3 > 0.f ? x3 : 0.1f * x3;
            }
            *reinterpret_cast<float4*>(&C[(size_t)m * N + gn]) = make_float4(x0, x1, x2, x3);
        }
        int gn2 = n0 + BN / 2 + tx * 4;
        if (N % BN == 0 || gn2 < N) {
            unpack2(acc[i][2], x0, x1);
            unpack2(acc[i][3], x2, x3);
            x0 += bb; x1 += bb; x2 += bb; x3 += bb;
            if (LRELU) {
                x0 = x0 > 0.f ? x0 : 0.1f * x0;
                x1 = x1 > 0.f ? x1 : 0.1f * x1;
                x2 = x2 > 0.f ? x2 : 0.1f * x2;
                x3 = x3 > 0.f ? x3 : 0.1f * x3;
            }
            *reinterpret_cast<float4*>(&C[(size_t)m * N + gn2]) = make_float4(x0, x1, x2, x3);
        }
    }
}

// ---------------- main GEMM: 8x8 micro-tile, register prefetch, split-K ----
// C[M][N] = A[M][K]*B[K][N]; SK>1 -> writes partials (no bias) to C (layout
// [sk][M][N]); SK==1 -> bias + optional leaky relu.
template <int M, int N, int K, int BM, int BN, int SK, int THREADS, bool LRELU>
__global__ void __launch_bounds__(THREADS)
gemm8_kernel(const float* __restrict__ A, const float* __restrict__ B,
             const float* __restrict__ bias, float* __restrict__ C)
{
    constexpr int BK = 16;
    constexpr int TX = BN / 8;
    constexpr int TY = BM / 8;
    static_assert(TX * TY == THREADS, "threads");
    constexpr int KC = K / SK;
    static_assert(KC % BK == 0, "K chunk");
    static_assert(N % 8 == 0, "N align");
    constexpr int NB4 = BN / 4;
    constexpr int AE = BM * BK / THREADS;
    constexpr int BE = BK * NB4 / THREADS;

    __shared__ __align__(16) float  As[BK][BM + 4];
    __shared__ __align__(16) float4 Bs4[BK][NB4];

    const int tid = threadIdx.x;
    const int tx  = tid % TX;
    const int ty  = tid / TX;
    const int m0  = blockIdx.y * BM;
    const int n0  = blockIdx.x * BN;
    const int k00 = blockIdx.z * KC;

    float  ar[AE];
    float4 br[BE];

    u64 acc[8][4];
    #pragma unroll
    for (int i = 0; i < 8; i++)
        #pragma unroll
        for (int j = 0; j < 4; j++) acc[i][j] = pack2(0.f, 0.f);

    // ---- stage 0 load
    #pragma unroll
    for (int j = 0; j < AE; j++) {
        int i = tid + j * THREADS;
        int kk = i % BK, m = i / BK;
        float v = 0.f;
        if (M % BM == 0 || (m0 + m) < M) v = A[(size_t)(m0 + m) * K + k00 + kk];
        ar[j] = v;
    }
    #pragma unroll
    for (int j = 0; j < BE; j++) {
        int i = tid + j * THREADS;
        int n4 = i % NB4, kk = i / NB4;
        int gn = n0 + n4 * 4;
        float4 v = make_float4(0.f, 0.f, 0.f, 0.f);
        if (N % BN == 0 || gn < N)
            v = *reinterpret_cast<const float4*>(&B[(size_t)(k00 + kk) * N + gn]);
        br[j] = v;
    }
    #pragma unroll
    for (int j = 0; j < AE; j++) {
        int i = tid + j * THREADS;
        As[i % BK][i / BK] = ar[j];
    }
    #pragma unroll
    for (int j = 0; j < BE; j++) {
        int i = tid + j * THREADS;
        Bs4[i / NB4][i % NB4] = br[j];
    }
    __syncthreads();

    for (int kt = 0; kt < KC; kt += BK) {
        const bool has_next = (kt + BK) < KC;
        if (has_next) {
            #pragma unroll
            for (int j = 0; j < AE; j++) {
                int i = tid + j * THREADS;
                int kk = i % BK, m = i / BK;
                float v = 0.f;
                if (M % BM == 0 || (m0 + m) < M)
                    v = A[(size_t)(m0 + m) * K + k00 + kt + BK + kk];
                ar[j] = v;
            }
            #pragma unroll
            for (int j = 0; j < BE; j++) {
                int i = tid + j * THREADS;
                int n4 = i % NB4, kk = i / NB4;
                int gn = n0 + n4 * 4;
                float4 v = make_float4(0.f, 0.f, 0.f, 0.f);
                if (N % BN == 0 || gn < N)
                    v = *reinterpret_cast<const float4*>(&B[(size_t)(k00 + kt + BK + kk) * N + gn]);
                br[j] = v;
            }
        }

        #pragma unroll
        for (int kk = 0; kk < BK; kk++) {
            float4 a0 = *reinterpret_cast<const float4*>(&As[kk][ty * 8]);
            float4 a1 = *reinterpret_cast<const float4*>(&As[kk][ty * 8 + 4]);
            float4 bA = Bs4[kk][tx * 2];
            float4 bB = Bs4[kk][tx * 2 + 1];
            u64 b01 = pack2(bA.x, bA.y);
            u64 b23 = pack2(bA.z, bA.w);
            u64 b45 = pack2(bB.x, bB.y);
            u64 b67 = pack2(bB.z, bB.w);
            float av[8] = {a0.x, a0.y, a0.z, a0.w, a1.x, a1.y, a1.z, a1.w};
            #pragma unroll
            for (int i = 0; i < 8; i++) {
                u64 ap = pack2(av[i], av[i]);
                acc[i][0] = fma2(ap, b01, acc[i][0]);
                acc[i][1] = fma2(ap, b23, acc[i][1]);
                acc[i][2] = fma2(ap, b45, acc[i][2]);
                acc[i][3] = fma2(ap, b67, acc[i][3]);
            }
        }
        __syncthreads();
        if (has_next) {
            #pragma unroll
            for (int j = 0; j < AE; j++) {
                int i = tid + j * THREADS;
                As[i % BK][i / BK] = ar[j];
            }
            #pragma unroll
            for (int j = 0; j < BE; j++) {
                int i = tid + j * THREADS;
                Bs4[i / NB4][i % NB4] = br[j];
            }
            __syncthreads();
        }
    }

    // ---- epilogue
    float* Cb = (SK == 1) ? C : (C + (size_t)blockIdx.z * M * N);
    #pragma unroll
    for (int i = 0; i < 8; i++) {
        int m = m0 + ty * 8 + i;
        if (M % BM != 0 && m >= M) continue;
        int gn = n0 + tx * 8;
        if (N % BN != 0 && gn >= N) continue;
        float x0, x1, x2, x3, x4, x5, x6, x7;
        unpack2(acc[i][0], x0, x1);
        unpack2(acc[i][1], x2, x3);
        unpack2(acc[i][2], x4, x5);
        unpack2(acc[i][3], x6, x7);
        if (SK == 1) {
            float bb = bias[m];
            x0 += bb; x1 += bb; x2 += bb; x3 += bb;
            x4 += bb; x5 += bb; x6 += bb; x7 += bb;
            if (LRELU) {
                x0 = x0 > 0.f ? x0 : 0.1f * x0;
                x1 = x1 > 0.f ? x1 : 0.1f * x1;
                x2 = x2 > 0.f ? x2 : 0.1f * x2;
                x3 = x3 > 0.f ? x3 : 0.1f * x3;
                x4 = x4 > 0.f ? x4 : 0.1f * x4;
                x5 = x5 > 0.f ? x5 : 0.1f * x5;
                x6 = x6 > 0.f ? x6 : 0.1f * x6;
                x7 = x7 > 0.f ? x7 : 0.1f * x7;
            }
        }
        *reinterpret_cast<float4*>(&Cb[(size_t)m * N + gn])     = make_float4(x0, x1, x2, x3);
        *reinterpret_cast<float4*>(&Cb[(size_t)m * N + gn + 4]) = make_float4(x4, x5, x6, x7);
    }
}

// ---------------- split-K reduce: C = sum_sk part + bias (+lrelu) ----------
template <int M, int N, int SK, bool LRELU>
__global__ void reduce_kernel(const float* __restrict__ part,
                              const float* __restrict__ bias,
                              float* __restrict__ C)
{
    int i4 = (blockIdx.x * 256 + threadIdx.x) * 4;
    if (i4 >= M * N) return;
    float4 s = *reinterpret_cast<const float4*>(&part[i4]);
    #pragma unroll
    for (int sk = 1; sk < SK; sk++) {
        float4 p = *reinterpret_cast<const float4*>(&part[(size_t)sk * M * N + i4]);
        s.x += p.x; s.y += p.y; s.z += p.z; s.w += p.w;
    }
    float bb = bias[i4 / N];
    s.x += bb; s.y += bb; s.z += bb; s.w += bb;
    if (LRELU) {
        s.x = s.x > 0.f ? s.x : 0.1f * s.x;
        s.y = s.y > 0.f ? s.y : 0.1f * s.y;
        s.z = s.z > 0.f ? s.z : 0.1f * s.z;
        s.w = s.w > 0.f ? s.w : 0.1f * s.w;
    }
    *reinterpret_cast<float4*>(&C[i4]) = s;
}

// ---------------- decode: feat (CNHW) -> candidate record ----------------
__device__ __forceinline__ float sigmoidf_(float x) { return 1.f / (1.f + expf(-x)); }

__global__ void decode_kernel(const float* __restrict__ feat1,
                              const float* __restrict__ feat2,
                              float* __restrict__ cand)
{
    int idx = blockIdx.x * blockDim.x + threadIdx.x;
    if (idx >= BATCH * NCAND) return;
    int b = idx / NCAND;
    int n = idx - b * NCAND;

    const float A1w[3] = {81.f, 135.f, 344.f}, A1h[3] = {82.f, 169.f, 319.f};
    const float A2w[3] = {10.f, 23.f,  37.f},  A2h[3] = {14.f, 27.f,  58.f};

    const float* base;
    int H, W, a, yy, xx;
    size_t estr;
    float aw, ah;
    if (n < 507) {
        H = 13; W = 13;
        a = n / 169; int r = n - a * 169; yy = r / 13; xx = r - yy * 13;
        aw = A1w[a]; ah = A1h[a];
        estr = (size_t)BATCH * 169;
        base = feat1 + (size_t)(a * 85) * estr + b * 169 + yy * 13 + xx;
    } else {
        int m = n - 507;
        H = 26; W = 26;
        a = m / 676; int r = m - a * 676; yy = r / 26; xx = r - yy * 26;
        aw = A2w[a]; ah = A2h[a];
        estr = (size_t)BATCH * 676;
        base = feat2 + (size_t)(a * 85) * estr + b * 676 + yy * 26 + xx;
    }

    float t0 = base[0];
    float t1 = base[estr];
    float t2 = base[2 * estr];
    float t3 = base[3 * estr];
    float t4 = base[4 * estr];

    float bx = (sigmoidf_(t0) + (float)xx) / (float)W;
    float by = (sigmoidf_(t1) + (float)yy) / (float)H;
    float bw = expf(t2) * aw / 416.f;
    float bh = expf(t3) * ah / 416.f;
    float obj = sigmoidf_(t4);

    float ml = base[5 * estr];
    int lab = 0;
    for (int c = 1; c < 80; c++) {
        float v = base[(5 + c) * estr];
        if (v > ml) { ml = v; lab = c; }
    }
    float cc = sigmoidf_(ml);
    float score = obj * cc;
    if (!(score >= 0.1f)) score = 0.f;

    float* o = cand + (size_t)idx * 8;
    o[0] = (by - bh * 0.5f) * 416.f;
    o[1] = (bx - bw * 0.5f) * 416.f;
    o[2] = (by + bh * 0.5f) * 416.f;
    o[3] = (bx + bw * 0.5f) * 416.f;
    o[4] = obj;
    o[5] = cc;
    o[6] = (float)lab;
    o[7] = score;
}

// ---------------- per-image top-k + greedy NMS ----------------
__device__ __forceinline__ void argmax2(float& v, int& i, float v2, int i2)
{
    if (v2 > v || (v2 == v && i2 < i)) { v = v2; i = i2; }
}

__global__ void nms_kernel(const float* __restrict__ cand, float* __restrict__ out)
{
    const int b = blockIdx.x;
    const int tid = threadIdx.x; // 512 threads
    const int lane = tid & 31;
    const int wid  = tid >> 5;   // 16 warps

    __shared__ float s[NCAND];
    __shared__ int   sel[TOPK];
    __shared__ float wv[16];
    __shared__ int   wi[16];

    const float* cb = cand + (size_t)b * NCAND * 8;
    for (int i = tid; i < NCAND; i += 512) s[i] = cb[i * 8 + 7];
    __syncthreads();

    for (int r = 0; r < TOPK; r++) {
        float bv = -1.f; int bi = NCAND + 1;
        for (int i = tid; i < NCAND; i += 512)
            argmax2(bv, bi, s[i], i);
        #pragma unroll
        for (int o = 16; o > 0; o >>= 1) {
            float v2 = __shfl_down_sync(0xffffffffu, bv, o);
            int   i2 = __shfl_down_sync(0xffffffffu, bi, o);
            argmax2(bv, bi, v2, i2);
        }
        if (lane == 0) { wv[wid] = bv; wi[wid] = bi; }
        __syncthreads();
        if (wid == 0) {
            float v = (lane < 16) ? wv[lane] : -3.f;
            int   i = (lane < 16) ? wi[lane] : NCAND + 2;
            #pragma unroll
            for (int o = 8; o > 0; o >>= 1) {
                float v2 = __shfl_down_sync(0xffffffffu, v, o);
                int   i2 = __shfl_down_sync(0xffffffffu, i, o);
                argmax2(v, i, v2, i2);
            }
            if (lane == 0) { sel[r] = i; s[i] = -2.f; }
        }
        __syncthreads();
    }

    __shared__ float y0s[TOPK], x0s[TOPK], y1s[TOPK], x1s[TOPK], areas[TOPK];
    __shared__ int labs[TOPK];
    __shared__ unsigned char keep[TOPK];
    if (tid < TOPK) {
        int ii = sel[tid];
        float y0 = cb[ii * 8 + 0], x0 = cb[ii * 8 + 1];
        float y1 = cb[ii * 8 + 2], x1 = cb[ii * 8 + 3];
        y0s[tid] = y0; x0s[tid] = x0; y1s[tid] = y1; x1s[tid] = x1;
        areas[tid] = (y1 - y0) * (x1 - x0);
        labs[tid] = (int)cb[ii * 8 + 6];
        keep[tid] = (cb[ii * 8 + 7] > 0.f) ? 1 : 0;
    }
    __syncthreads();

    for (int j = 0; j < TOPK - 1; j++) {
        if (tid > j && tid < TOPK && keep[j] && keep[tid] && labs[tid] == labs[j]) {
            float ty0 = fmaxf(y0s[tid], y0s[j]);
            float tx0 = fmaxf(x0s[tid], x0s[j]);
            float ty1 = fminf(y1s[tid], y1s[j]);
            float tx1 = fminf(x1s[tid], x1s[j]);
            float ih = fmaxf(ty1 - ty0, 0.f);
            float iw = fmaxf(tx1 - tx0, 0.f);
            float inter = ih * iw;
            float iou = inter / (areas[tid] + areas[j] - inter + 1e-9f);
            if (iou > 0.5f) keep[tid] = 0;
        }
        __syncthreads();
    }

    if (tid < TOPK) {
        float* o = out + ((size_t)b * TOPK + tid) * 7;
        if (keep[tid]) {
            int ii = sel[tid];
            o[0] = y0s[tid]; o[1] = x0s[tid]; o[2] = y1s[tid]; o[3] = x1s[tid];
            o[4] = cb[ii * 8 + 4];
            o[5] = cb[ii * 8 + 5];
            o[6] = (float)labs[tid];
        } else {
            #pragma unroll
            for (int k = 0; k < 7; k++) o[k] = 0.f;
        }
    }
}

// ---------------- launch ----------------
static inline int ceil_div(int a, int b) { return (a + b - 1) / b; }

extern "C" void kernel_launch(void* const* d_in, const int* in_sizes, int n_in,
                              void* d_out, int out_size)
{
    (void)in_sizes; (void)n_in; (void)out_size;
    const float* images = (const float*)d_in[0];
    const float* w1 = (const float*)d_in[1];  const float* b1 = (const float*)d_in[2];
    const float* w2 = (const float*)d_in[3];  const float* b2 = (const float*)d_in[4];
    const float* w3 = (const float*)d_in[5];  const float* b3 = (const float*)d_in[6];
    const float* w4 = (const float*)d_in[7];  const float* b4 = (const float*)d_in[8];
    const float* w5 = (const float*)d_in[9];  const float* b5 = (const float*)d_in[10];
    const float* wh1 = (const float*)d_in[11]; const float* bh1 = (const float*)d_in[12];
    const float* wh2 = (const float*)d_in[13]; const float* bh2 = (const float*)d_in[14];
    float* out = (float*)d_out;

    static float *act1 = nullptr, *act2, *act3, *act4, *act5, *feat1, *feat2, *col, *cand;
    if (!act1) {
        cudaGetSymbolAddress((void**)&act1, g_act1);
        cudaGetSymbolAddress((void**)&act2, g_act2);
        cudaGetSymbolAddress((void**)&act3, g_act3);
        cudaGetSymbolAddress((void**)&act4, g_act4);
        cudaGetSymbolAddress((void**)&act5, g_act5);
        cudaGetSymbolAddress((void**)&feat1, g_feat1);
        cudaGetSymbolAddress((void**)&feat2, g_feat2);
        cudaGetSymbolAddress((void**)&col,  g_col);
        cudaGetSymbolAddress((void**)&cand, g_cand);
    }
    float* part = col + PARTIAL_OFF;

    // --- L1: 3->32, 416->208  (N = 346112, K = 27)
    im2col_kernel<3, 416, 416, 208, 208, true>
        <<<dim3(ceil_div(346112, 256), 27), 256>>>(images, col);
    gemm_kernel<32, 346112, 27, 32, 128, 2, true>
        <<<dim3(346112 / 128, 1), 256>>>(w1, col, b1, act1);

    // --- L2: 32->64, 208->104 (N = 86528, K = 288)
    im2col_kernel<32, 208, 208, 104, 104, false>
        <<<dim3(ceil_div(86528, 256), 288), 256>>>(act1, col);
    gemm8_kernel<64, 86528, 288, 64, 128, 1, 128, true>
        <<<dim3(86528 / 128, 1, 1), 128>>>(w2, col, b2, act2);

    // --- L3: 64->128, 104->52 (N = 21632, K = 576)
    im2col_kernel<64, 104, 104, 52, 52, false>
        <<<dim3(ceil_div(21632, 256), 576), 256>>>(act2, col);
    gemm8_kernel<128, 21632, 576, 64, 128, 1, 128, true>
        <<<dim3(21632 / 128, 2, 1), 128>>>(w3, col, b3, act3);

    // --- L4: 128->256, 52->26 (N = 5408, K = 1152), split-K 2
    im2col_kernel<128, 52, 52, 26, 26, false>
        <<<dim3(ceil_div(5408, 256), 1152), 256>>>(act3, col);
    gemm8_kernel<256, 5408, 1152, 64, 128, 2, 128, false>
        <<<dim3(ceil_div(5408, 128), 4, 2), 128>>>(w4, col, b4, part);
    reduce_kernel<256, 5408, 2, true>
        <<<ceil_div(256 * 5408 / 4, 256), 256>>>(part, b4, act4);

    // --- head2: 255 x 5408, K = 256
    gemm8_kernel<255, 5408, 256, 64, 128, 1, 128, false>
        <<<dim3(ceil_div(5408, 128), 4, 1), 128>>>(wh2, act4, bh2, feat2);

    // --- L5: 256->512, 26->13 (N = 1352, K = 2304), split-K 4
    im2col_kernel<256, 26, 26, 13, 13, false>
        <<<dim3(ceil_div(1352, 256), 2304), 256>>>(act4, col);
    gemm8_kernel<512, 1352, 2304, 64, 128, 4, 128, false>
        <<<dim3(ceil_div(1352, 128), 8, 4), 128>>>(w5, col, b5, part);
    reduce_kernel<512, 1352, 4, true>
        <<<ceil_div(512 * 1352 / 4, 256), 256>>>(part, b5, act5);

    // --- head1: 255 x 1352, K = 512
    gemm8_kernel<255, 1352, 512, 64, 64, 1, 64, false>
        <<<dim3(ceil_div(1352, 64), 4, 1), 64>>>(wh1, act5, bh1, feat1);

    // --- decode + nms
    decode_kernel<<<ceil_div(BATCH * NCAND, 256), 256>>>(feat1, feat2, cand);
    nms_kernel<<<BATCH, 512>>>(cand, out);
}

// round 7
// speedup vs baseline: 1.8164x; 1.0696x over previous
#include <cuda_runtime.h>
#include <cstdint>

#define BATCH 8
#define NCAND 2535   // 3*13*13 + 3*26*26
#define TOPK 300

typedef unsigned long long u64;

__device__ __forceinline__ u64 pack2(float x, float y) {
    u64 r;
    asm("mov.b64 %0, {%1, %2};" : "=l"(r)
        : "r"(__float_as_uint(x)), "r"(__float_as_uint(y)));
    return r;
}
__device__ __forceinline__ void unpack2(u64 v, float& x, float& y) {
    unsigned a, b;
    asm("mov.b64 {%0, %1}, %2;" : "=r"(a), "=r"(b) : "l"(v));
    x = __uint_as_float(a); y = __uint_as_float(b);
}
__device__ __forceinline__ u64 fma2(u64 a, u64 b, u64 c) {
    u64 d;
    asm("fma.rn.f32x2 %0, %1, %2, %3;" : "=l"(d) : "l"(a), "l"(b), "l"(c));
    return d;
}
__device__ __forceinline__ unsigned smem_u32(const void* p) {
    return (unsigned)__cvta_generic_to_shared(p);
}
__device__ __forceinline__ void cp_async16(unsigned dst, const void* src, bool valid) {
    int sz = valid ? 16 : 0;
    asm volatile("cp.async.ca.shared.global [%0], [%1], 16, %2;\n"
                 :: "r"(dst), "l"(src), "r"(sz) : "memory");
}
__device__ __forceinline__ void cp_commit() {
    asm volatile("cp.async.commit_group;\n" ::: "memory");
}
__device__ __forceinline__ void cp_wait0() {
    asm volatile("cp.async.wait_group 0;\n" ::: "memory");
}

// ---------------- scratch (device globals; no allocation) ----------------
__device__ float g_act1[32  * BATCH * 208 * 208];
__device__ float g_act2[64  * BATCH * 104 * 104];
__device__ float g_act3[128 * BATCH * 52  * 52];
__device__ float g_act4[256 * BATCH * 26  * 26];
__device__ float g_act5[512 * BATCH * 13  * 13];
__device__ float g_feat1[255 * BATCH * 13 * 13];
__device__ float g_feat2[255 * BATCH * 26 * 26];
__device__ float g_col[25000000];   // im2col scratch + split-K partials @ +10M
__device__ float g_cand[BATCH * NCAND * 8];

#define PARTIAL_OFF 10000000

// ---------------- im2col: in -> col[K9][BATCH*P] ----------------
template <int CIN, int HIN, int WIN, int HOUT, int WOUT, bool NCHW>
__global__ void im2col_kernel(const float* __restrict__ in, float* __restrict__ col)
{
    constexpr int P = HOUT * WOUT;
    constexpr int NN = BATCH * P;
    constexpr int HWIN = HIN * WIN;
    const int k = blockIdx.y;
    const int n = blockIdx.x * 256 + threadIdx.x;
    if (n >= NN) return;
    const int c  = k / 9;
    const int t  = k - 9 * c;
    const int ky = t / 3;
    const int kx = t - 3 * ky;
    const int b  = n / P;
    const int p  = n - b * P;
    const int oy = p / WOUT;
    const int ox = p - oy * WOUT;
    const int iy = 2 * oy + ky;
    const int ix = 2 * ox + kx;
    float v = 0.f;
    if (iy < HIN && ix < WIN) {
        v = NCHW ? in[((size_t)(b * CIN + c) * HIN + iy) * WIN + ix]
                 : in[(size_t)(c * BATCH + b) * HWIN + iy * WIN + ix];
    }
    col[(size_t)k * NN + n] = v;
}

// ---------------- small-M GEMM for L1 (K=27, M=32) ----------------
template <int M, int N, int K, int BM, int BN, int TM, bool LRELU>
__global__ void __launch_bounds__(256)
gemm_kernel(const float* __restrict__ A, const float* __restrict__ B,
            const float* __restrict__ bias, float* __restrict__ C)
{
    constexpr int BK = 16;
    constexpr int TX = BN / 8;
    constexpr int TY = BM / TM;
    static_assert(TX * TY == 256, "thread count");
    constexpr int NB4 = BN / 4;

    __shared__ __align__(16) float  As[BK][BM + 4];
    __shared__ __align__(16) float4 Bs4[BK][NB4];

    const int tid = threadIdx.x;
    const int tx  = tid % TX;
    const int ty  = tid / TX;
    const int m0  = blockIdx.y * BM;
    const int n0  = blockIdx.x * BN;

    u64 acc[TM][4];
    #pragma unroll
    for (int i = 0; i < TM; i++)
        #pragma unroll
        for (int j = 0; j < 4; j++) acc[i][j] = pack2(0.f, 0.f);

    for (int kt = 0; kt < K; kt += BK) {
        #pragma unroll
        for (int i = tid; i < BM * BK; i += 256) {
            int m  = i >> 4;
            int kk = i & 15;
            float v = 0.f;
            bool ok = true;
            if (M % BM != 0) ok = (m0 + m) < M;
            if (K % BK != 0) ok = ok && (kt + kk) < K;
            if (ok) v = A[(size_t)(m0 + m) * K + kt + kk];
            As[kk][m] = v;
        }
        #pragma unroll
        for (int i = tid; i < BK * NB4; i += 256) {
            int kk = i / NB4;
            int n4 = i - kk * NB4;
            int gn = n0 + n4 * 4;
            float4 v = make_float4(0.f, 0.f, 0.f, 0.f);
            bool ok = true;
            if (K % BK != 0) ok = (kt + kk) < K;
            if (N % BN != 0) ok = ok && (gn < N);
            if (ok) v = *reinterpret_cast<const float4*>(&B[(size_t)(kt + kk) * N + gn]);
            Bs4[kk][n4] = v;
        }
        __syncthreads();

        #pragma unroll
        for (int kk = 0; kk < BK; kk++) {
            float4 bfa = Bs4[kk][tx];
            float4 bfb = Bs4[kk][NB4 / 2 + tx];
            u64 b01 = pack2(bfa.x, bfa.y);
            u64 b23 = pack2(bfa.z, bfa.w);
            u64 b45 = pack2(bfb.x, bfb.y);
            u64 b67 = pack2(bfb.z, bfb.w);
            float av[TM];
            float2 a2 = *reinterpret_cast<const float2*>(&As[kk][ty * 2]);
            av[0] = a2.x; av[1] = a2.y;
            #pragma unroll
            for (int i = 0; i < TM; i++) {
                u64 a2p = pack2(av[i], av[i]);
                acc[i][0] = fma2(a2p, b01, acc[i][0]);
                acc[i][1] = fma2(a2p, b23, acc[i][1]);
                acc[i][2] = fma2(a2p, b45, acc[i][2]);
                acc[i][3] = fma2(a2p, b67, acc[i][3]);
            }
        }
        __syncthreads();
    }

    #pragma unroll
    for (int i = 0; i < TM; i++) {
        int m = m0 + ty * TM + i;
        if (M % BM != 0 && m >= M) continue;
        float bb = bias[m];
        float x0, x1, x2, x3;
        int gn = n0 + tx * 4;
        if (N % BN == 0 || gn < N) {
            unpack2(acc[i][0], x0, x1);
            unpack2(acc[i][1], x2, x3);
            x0 += bb; x1 += bb; x2 += bb; x3 += bb;
            if (LRELU) {
                x0 = x0 > 0.f ? x0 : 0.1f * x0;
                x1 = x1 > 0.f ? x1 : 0.1f * x1;
                x2 = x2 > 0.f ? x2 : 0.1f * x2;
                x3 = x3 > 0.f ? x3 : 0.1f * x3;
            }
            *reinterpret_cast<float4*>(&C[(size_t)m * N + gn]) = make_float4(x0, x1, x2, x3);
        }
        int gn2 = n0 + BN / 2 + tx * 4;
        if (N % BN == 0 || gn2 < N) {
            unpack2(acc[i][2], x0, x1);
            unpack2(acc[i][3], x2, x3);
            x0 += bb; x1 += bb; x2 += bb; x3 += bb;
            if (LRELU) {
                x0 = x0 > 0.f ? x0 : 0.1f * x0;
                x1 = x1 > 0.f ? x1 : 0.1f * x1;
                x2 = x2 > 0.f ? x2 : 0.1f * x2;
                x3 = x3 > 0.f ? x3 : 0.1f * x3;
            }
            *reinterpret_cast<float4*>(&C[(size_t)m * N + gn2]) = make_float4(x0, x1, x2, x3);
        }
    }
}

// ---------------- main GEMM v3: 8x8 tile, cp.async B, smem double-buffer ---
// C[M][N] = A[M][K]*B[K][N]; SK>1 -> partials (no bias) at C[sk][M][N].
template <int M, int N, int K, int BM, int BN, int SK, int THREADS, bool LRELU>
__global__ void __launch_bounds__(THREADS, 4)
gemm9_kernel(const float* __restrict__ A, const float* __restrict__ B,
             const float* __restrict__ bias, float* __restrict__ C)
{
    constexpr int BK = 16;
    constexpr int TX = BN / 8;
    constexpr int TY = BM / 8;
    static_assert(TX * TY == THREADS, "threads");
    constexpr int KC = K / SK;
    static_assert(KC % BK == 0, "K chunk must be multiple of BK");
    static_assert(N % 4 == 0, "N align");
    constexpr int NB4 = BN / 4;
    constexpr int AE  = BM * BK / THREADS;   // scalar A floats per thread
    constexpr int BE4 = BK * NB4 / THREADS;  // float4 B per thread

    __shared__ __align__(16) float  As[2][BK][BM + 4];
    __shared__ __align__(16) float4 Bs[2][BK][NB4];

    const int tid = threadIdx.x;
    const int tx  = tid % TX;
    const int ty  = tid / TX;
    const int m0  = blockIdx.y * BM;
    const int n0  = blockIdx.x * BN;
    const int k00 = blockIdx.z * KC;

    float ar[AE];

    u64 acc[8][4];
    #pragma unroll
    for (int i = 0; i < 8; i++)
        #pragma unroll
        for (int j = 0; j < 4; j++) acc[i][j] = pack2(0.f, 0.f);

    // ---- prologue: stage 0
    #pragma unroll
    for (int j = 0; j < BE4; j++) {
        int i = tid + j * THREADS;
        int kk = i / NB4, n4 = i % NB4;
        int gn = n0 + n4 * 4;
        bool ok = (N % BN == 0) || (gn < N);
        const float* src = ok ? &B[(size_t)(k00 + kk) * N + gn] : B;
        cp_async16(smem_u32(&Bs[0][kk][n4]), src, ok);
    }
    cp_commit();
    #pragma unroll
    for (int j = 0; j < AE; j++) {
        int i = tid + j * THREADS;
        int kk = i % BK, m = i / BK;
        float v = 0.f;
        if (M % BM == 0 || (m0 + m) < M) v = A[(size_t)(m0 + m) * K + k00 + kk];
        ar[j] = v;
    }
    #pragma unroll
    for (int j = 0; j < AE; j++) {
        int i = tid + j * THREADS;
        As[0][i % BK][i / BK] = ar[j];
    }
    cp_wait0();
    __syncthreads();

    int buf = 0;
    for (int kt = 0; kt < KC; kt += BK) {
        const bool has_next = (kt + BK) < KC;
        if (has_next) {
            #pragma unroll
            for (int j = 0; j < BE4; j++) {
                int i = tid + j * THREADS;
                int kk = i / NB4, n4 = i % NB4;
                int gn = n0 + n4 * 4;
                bool ok = (N % BN == 0) || (gn < N);
                const float* src = ok ? &B[(size_t)(k00 + kt + BK + kk) * N + gn] : B;
                cp_async16(smem_u32(&Bs[buf ^ 1][kk][n4]), src, ok);
            }
            cp_commit();
            #pragma unroll
            for (int j = 0; j < AE; j++) {
                int i = tid + j * THREADS;
                int kk = i % BK, m = i / BK;
                float v = 0.f;
                if (M % BM == 0 || (m0 + m) < M)
                    v = A[(size_t)(m0 + m) * K + k00 + kt + BK + kk];
                ar[j] = v;
            }
        }

        #pragma unroll
        for (int kk = 0; kk < BK; kk++) {
            float4 a0 = *reinterpret_cast<const float4*>(&As[buf][kk][ty * 8]);
            float4 a1 = *reinterpret_cast<const float4*>(&As[buf][kk][ty * 8 + 4]);
            float4 bA = Bs[buf][kk][tx * 2];
            float4 bB = Bs[buf][kk][tx * 2 + 1];
            u64 b01 = pack2(bA.x, bA.y);
            u64 b23 = pack2(bA.z, bA.w);
            u64 b45 = pack2(bB.x, bB.y);
            u64 b67 = pack2(bB.z, bB.w);
            float av[8] = {a0.x, a0.y, a0.z, a0.w, a1.x, a1.y, a1.z, a1.w};
            #pragma unroll
            for (int i = 0; i < 8; i++) {
                u64 ap = pack2(av[i], av[i]);
                acc[i][0] = fma2(ap, b01, acc[i][0]);
                acc[i][1] = fma2(ap, b23, acc[i][1]);
                acc[i][2] = fma2(ap, b45, acc[i][2]);
                acc[i][3] = fma2(ap, b67, acc[i][3]);
            }
        }

        if (has_next) {
            #pragma unroll
            for (int j = 0; j < AE; j++) {
                int i = tid + j * THREADS;
                As[buf ^ 1][i % BK][i / BK] = ar[j];
            }
            cp_wait0();
            __syncthreads();
            buf ^= 1;
        }
    }

    // ---- epilogue
    float* Cb = (SK == 1) ? C : (C + (size_t)blockIdx.z * M * N);
    #pragma unroll
    for (int i = 0; i < 8; i++) {
        int m = m0 + ty * 8 + i;
        if (M % BM != 0 && m >= M) continue;
        int gn = n0 + tx * 8;
        if (N % BN != 0 && gn >= N) continue;
        float x0, x1, x2, x3, x4, x5, x6, x7;
        unpack2(acc[i][0], x0, x1);
        unpack2(acc[i][1], x2, x3);
        unpack2(acc[i][2], x4, x5);
        unpack2(acc[i][3], x6, x7);
        if (SK == 1) {
            float bb = bias[m];
            x0 += bb; x1 += bb; x2 += bb; x3 += bb;
            x4 += bb; x5 += bb; x6 += bb; x7 += bb;
            if (LRELU) {
                x0 = x0 > 0.f ? x0 : 0.1f * x0;
                x1 = x1 > 0.f ? x1 : 0.1f * x1;
                x2 = x2 > 0.f ? x2 : 0.1f * x2;
                x3 = x3 > 0.f ? x3 : 0.1f * x3;
                x4 = x4 > 0.f ? x4 : 0.1f * x4;
                x5 = x5 > 0.f ? x5 : 0.1f * x5;
                x6 = x6 > 0.f ? x6 : 0.1f * x6;
                x7 = x7 > 0.f ? x7 : 0.1f * x7;
            }
        }
        *reinterpret_cast<float4*>(&Cb[(size_t)m * N + gn])     = make_float4(x0, x1, x2, x3);
        *reinterpret_cast<float4*>(&Cb[(size_t)m * N + gn + 4]) = make_float4(x4, x5, x6, x7);
    }
}

// ---------------- split-K reduce: C = sum_sk part + bias (+lrelu) ----------
template <int M, int N, int SK, bool LRELU>
__global__ void reduce_kernel(const float* __restrict__ part,
                              const float* __restrict__ bias,
                              float* __restrict__ C)
{
    int i4 = (blockIdx.x * 256 + threadIdx.x) * 4;
    if (i4 >= M * N) return;
    float4 s = *reinterpret_cast<const float4*>(&part[i4]);
    #pragma unroll
    for (int sk = 1; sk < SK; sk++) {
        float4 p = *reinterpret_cast<const float4*>(&part[(size_t)sk * M * N + i4]);
        s.x += p.x; s.y += p.y; s.z += p.z; s.w += p.w;
    }
    float bb = bias[i4 / N];
    s.x += bb; s.y += bb; s.z += bb; s.w += bb;
    if (LRELU) {
        s.x = s.x > 0.f ? s.x : 0.1f * s.x;
        s.y = s.y > 0.f ? s.y : 0.1f * s.y;
        s.z = s.z > 0.f ? s.z : 0.1f * s.z;
        s.w = s.w > 0.f ? s.w : 0.1f * s.w;
    }
    *reinterpret_cast<float4*>(&C[i4]) = s;
}

// ---------------- decode: feat (CNHW) -> candidate record ----------------
__device__ __forceinline__ float sigmoidf_(float x) { return 1.f / (1.f + expf(-x)); }

__global__ void decode_kernel(const float* __restrict__ feat1,
                              const float* __restrict__ feat2,
                              float* __restrict__ cand)
{
    int idx = blockIdx.x * blockDim.x + threadIdx.x;
    if (idx >= BATCH * NCAND) return;
    int b = idx / NCAND;
    int n = idx - b * NCAND;

    const float A1w[3] = {81.f, 135.f, 344.f}, A1h[3] = {82.f, 169.f, 319.f};
    const float A2w[3] = {10.f, 23.f,  37.f},  A2h[3] = {14.f, 27.f,  58.f};

    const float* base;
    int H, W, a, yy, xx;
    size_t estr;
    float aw, ah;
    if (n < 507) {
        H = 13; W = 13;
        a = n / 169; int r = n - a * 169; yy = r / 13; xx = r - yy * 13;
        aw = A1w[a]; ah = A1h[a];
        estr = (size_t)BATCH * 169;
        base = feat1 + (size_t)(a * 85) * estr + b * 169 + yy * 13 + xx;
    } else {
        int m = n - 507;
        H = 26; W = 26;
        a = m / 676; int r = m - a * 676; yy = r / 26; xx = r - yy * 26;
        aw = A2w[a]; ah = A2h[a];
        estr = (size_t)BATCH * 676;
        base = feat2 + (size_t)(a * 85) * estr + b * 676 + yy * 26 + xx;
    }

    float t0 = base[0];
    float t1 = base[estr];
    float t2 = base[2 * estr];
    float t3 = base[3 * estr];
    float t4 = base[4 * estr];

    float bx = (sigmoidf_(t0) + (float)xx) / (float)W;
    float by = (sigmoidf_(t1) + (float)yy) / (float)H;
    float bw = expf(t2) * aw / 416.f;
    float bh = expf(t3) * ah / 416.f;
    float obj = sigmoidf_(t4);

    float ml = base[5 * estr];
    int lab = 0;
    for (int c = 1; c < 80; c++) {
        float v = base[(5 + c) * estr];
        if (v > ml) { ml = v; lab = c; }
    }
    float cc = sigmoidf_(ml);
    float score = obj * cc;
    if (!(score >= 0.1f)) score = 0.f;

    float* o = cand + (size_t)idx * 8;
    o[0] = (by - bh * 0.5f) * 416.f;
    o[1] = (bx - bw * 0.5f) * 416.f;
    o[2] = (by + bh * 0.5f) * 416.f;
    o[3] = (bx + bw * 0.5f) * 416.f;
    o[4] = obj;
    o[5] = cc;
    o[6] = (float)lab;
    o[7] = score;
}

// ---------------- per-image top-k + greedy NMS ----------------
__device__ __forceinline__ void argmax2(float& v, int& i, float v2, int i2)
{
    if (v2 > v || (v2 == v && i2 < i)) { v = v2; i = i2; }
}

__global__ void nms_kernel(const float* __restrict__ cand, float* __restrict__ out)
{
    const int b = blockIdx.x;
    const int tid = threadIdx.x; // 512 threads
    const int lane = tid & 31;
    const int wid  = tid >> 5;   // 16 warps

    __shared__ float s[NCAND];
    __shared__ int   sel[TOPK];
    __shared__ float wv[16];
    __shared__ int   wi[16];

    const float* cb = cand + (size_t)b * NCAND * 8;
    for (int i = tid; i < NCAND; i += 512) s[i] = cb[i * 8 + 7];
    __syncthreads();

    for (int r = 0; r < TOPK; r++) {
        float bv = -1.f; int bi = NCAND + 1;
        for (int i = tid; i < NCAND; i += 512)
            argmax2(bv, bi, s[i], i);
        #pragma unroll
        for (int o = 16; o > 0; o >>= 1) {
            float v2 = __shfl_down_sync(0xffffffffu, bv, o);
            int   i2 = __shfl_down_sync(0xffffffffu, bi, o);
            argmax2(bv, bi, v2, i2);
        }
        if (lane == 0) { wv[wid] = bv; wi[wid] = bi; }
        __syncthreads();
        if (wid == 0) {
            float v = (lane < 16) ? wv[lane] : -3.f;
            int   i = (lane < 16) ? wi[lane] : NCAND + 2;
            #pragma unroll
            for (int o = 8; o > 0; o >>= 1) {
                float v2 = __shfl_down_sync(0xffffffffu, v, o);
                int   i2 = __shfl_down_sync(0xffffffffu, i, o);
                argmax2(v, i, v2, i2);
            }
            if (lane == 0) { sel[r] = i; s[i] = -2.f; }
        }
        __syncthreads();
    }

    __shared__ float y0s[TOPK], x0s[TOPK], y1s[TOPK], x1s[TOPK], areas[TOPK];
    __shared__ int labs[TOPK];
    __shared__ unsigned char keep[TOPK];
    if (tid < TOPK) {
        int ii = sel[tid];
        float y0 = cb[ii * 8 + 0], x0 = cb[ii * 8 + 1];
        float y1 = cb[ii * 8 + 2], x1 = cb[ii * 8 + 3];
        y0s[tid] = y0; x0s[tid] = x0; y1s[tid] = y1; x1s[tid] = x1;
        areas[tid] = (y1 - y0) * (x1 - x0);
        labs[tid] = (int)cb[ii * 8 + 6];
        keep[tid] = (cb[ii * 8 + 7] > 0.f) ? 1 : 0;
    }
    __syncthreads();

    for (int j = 0; j < TOPK - 1; j++) {
        if (tid > j && tid < TOPK && keep[j] && keep[tid] && labs[tid] == labs[j]) {
            float ty0 = fmaxf(y0s[tid], y0s[j]);
            float tx0 = fmaxf(x0s[tid], x0s[j]);
            float ty1 = fminf(y1s[tid], y1s[j]);
            float tx1 = fminf(x1s[tid], x1s[j]);
            float ih = fmaxf(ty1 - ty0, 0.f);
            float iw = fmaxf(tx1 - tx0, 0.f);
            float inter = ih * iw;
            float iou = inter / (areas[tid] + areas[j] - inter + 1e-9f);
            if (iou > 0.5f) keep[tid] = 0;
        }
        __syncthreads();
    }

    if (tid < TOPK) {
        float* o = out + ((size_t)b * TOPK + tid) * 7;
        if (keep[tid]) {
            int ii = sel[tid];
            o[0] = y0s[tid]; o[1] = x0s[tid]; o[2] = y1s[tid]; o[3] = x1s[tid];
            o[4] = cb[ii * 8 + 4];
            o[5] = cb[ii * 8 + 5];
            o[6] = (float)labs[tid];
        } else {
            #pragma unroll
            for (int k = 0; k < 7; k++) o[k] = 0.f;
        }
    }
}

// ---------------- launch ----------------
static inline int ceil_div(int a, int b) { return (a + b - 1) / b; }

extern "C" void kernel_launch(void* const* d_in, const int* in_sizes, int n_in,
                              void* d_out, int out_size)
{
    (void)in_sizes; (void)n_in; (void)out_size;
    const float* images = (const float*)d_in[0];
    const float* w1 = (const float*)d_in[1];  const float* b1 = (const float*)d_in[2];
    const float* w2 = (const float*)d_in[3];  const float* b2 = (const float*)d_in[4];
    const float* w3 = (const float*)d_in[5];  const float* b3 = (const float*)d_in[6];
    const float* w4 = (const float*)d_in[7];  const float* b4 = (const float*)d_in[8];
    const float* w5 = (const float*)d_in[9];  const float* b5 = (const float*)d_in[10];
    const float* wh1 = (const float*)d_in[11]; const float* bh1 = (const float*)d_in[12];
    const float* wh2 = (const float*)d_in[13]; const float* bh2 = (const float*)d_in[14];
    float* out = (float*)d_out;

    static float *act1 = nullptr, *act2, *act3, *act4, *act5, *feat1, *feat2, *col, *cand;
    if (!act1) {
        cudaGetSymbolAddress((void**)&act1, g_act1);
        cudaGetSymbolAddress((void**)&act2, g_act2);
        cudaGetSymbolAddress((void**)&act3, g_act3);
        cudaGetSymbolAddress((void**)&act4, g_act4);
        cudaGetSymbolAddress((void**)&act5, g_act5);
        cudaGetSymbolAddress((void**)&feat1, g_feat1);
        cudaGetSymbolAddress((void**)&feat2, g_feat2);
        cudaGetSymbolAddress((void**)&col,  g_col);
        cudaGetSymbolAddress((void**)&cand, g_cand);
    }
    float* part = col + PARTIAL_OFF;

    // --- L1: 3->32, 416->208  (N = 346112, K = 27)
    im2col_kernel<3, 416, 416, 208, 208, true>
        <<<dim3(ceil_div(346112, 256), 27), 256>>>(images, col);
    gemm_kernel<32, 346112, 27, 32, 128, 2, true>
        <<<dim3(346112 / 128, 1), 256>>>(w1, col, b1, act1);

    // --- L2: 32->64, 208->104 (N = 86528, K = 288)
    im2col_kernel<32, 208, 208, 104, 104, false>
        <<<dim3(ceil_div(86528, 256), 288), 256>>>(act1, col);
    gemm9_kernel<64, 86528, 288, 64, 128, 1, 128, true>
        <<<dim3(86528 / 128, 1, 1), 128>>>(w2, col, b2, act2);

    // --- L3: 64->128, 104->52 (N = 21632, K = 576)
    im2col_kernel<64, 104, 104, 52, 52, false>
        <<<dim3(ceil_div(21632, 256), 576), 256>>>(act2, col);
    gemm9_kernel<128, 21632, 576, 64, 128, 1, 128, true>
        <<<dim3(21632 / 128, 2, 1), 128>>>(w3, col, b3, act3);

    // --- L4: 128->256, 52->26 (N = 5408, K = 1152), split-K 2
    im2col_kernel<128, 52, 52, 26, 26, false>
        <<<dim3(ceil_div(5408, 256), 1152), 256>>>(act3, col);
    gemm9_kernel<256, 5408, 1152, 64, 128, 2, 128, false>
        <<<dim3(ceil_div(5408, 128), 4, 2), 128>>>(w4, col, b4, part);
    reduce_kernel<256, 5408, 2, true>
        <<<ceil_div(256 * 5408 / 4, 256), 256>>>(part, b4, act4);

    // --- head2: 255 x 5408, K = 256, split-K 2
    gemm9_kernel<255, 5408, 256, 64, 128, 2, 128, false>
        <<<dim3(ceil_div(5408, 128), 4, 2), 128>>>(wh2, act4, bh2, part);
    reduce_kernel<255, 5408, 2, false>
        <<<ceil_div(255 * 5408 / 4 + 1, 256), 256>>>(part, bh2, feat2);

    // --- L5: 256->512, 26->13 (N = 1352, K = 2304), split-K 4
    im2col_kernel<256, 26, 26, 13, 13, false>
        <<<dim3(ceil_div(1352, 256), 2304), 256>>>(act4, col);
    gemm9_kernel<512, 1352, 2304, 64, 128, 4, 128, false>
        <<<dim3(ceil_div(1352, 128), 8, 4), 128>>>(w5, col, b5, part);
    reduce_kernel<512, 1352, 4, true>
        <<<ceil_div(512 * 1352 / 4, 256), 256>>>(part, b5, act5);

    // --- head1: 255 x 1352, K = 512, split-K 4
    gemm9_kernel<255, 1352, 512, 64, 128, 4, 128, false>
        <<<dim3(ceil_div(1352, 128), 4, 4), 128>>>(wh1, act5, bh1, part);
    reduce_kernel<255, 1352, 4, false>
        <<<ceil_div(255 * 1352 / 4 + 1, 256), 256>>>(part, bh1, feat1);

    // --- decode + nms
    decode_kernel<<<ceil_div(BATCH * NCAND, 256), 256>>>(feat1, feat2, cand);
    nms_kernel<<<BATCH, 512>>>(cand, out);
}

// round 8
// speedup vs baseline: 1.8788x; 1.0344x over previous
#include <cuda_runtime.h>
#include <cstdint>

#define BATCH 8
#define NCAND 2535   // 3*13*13 + 3*26*26
#define TOPK 300
#define NPAD 4096

typedef unsigned long long u64;

__device__ __forceinline__ u64 pack2(float x, float y) {
    u64 r;
    asm("mov.b64 %0, {%1, %2};" : "=l"(r)
        : "r"(__float_as_uint(x)), "r"(__float_as_uint(y)));
    return r;
}
__device__ __forceinline__ void unpack2(u64 v, float& x, float& y) {
    unsigned a, b;
    asm("mov.b64 {%0, %1}, %2;" : "=r"(a), "=r"(b) : "l"(v));
    x = __uint_as_float(a); y = __uint_as_float(b);
}
__device__ __forceinline__ u64 fma2(u64 a, u64 b, u64 c) {
    u64 d;
    asm("fma.rn.f32x2 %0, %1, %2, %3;" : "=l"(d) : "l"(a), "l"(b), "l"(c));
    return d;
}
__device__ __forceinline__ unsigned smem_u32(const void* p) {
    return (unsigned)__cvta_generic_to_shared(p);
}
__device__ __forceinline__ void cp_async16(unsigned dst, const void* src, bool valid) {
    int sz = valid ? 16 : 0;
    asm volatile("cp.async.ca.shared.global [%0], [%1], 16, %2;\n"
                 :: "r"(dst), "l"(src), "r"(sz) : "memory");
}
__device__ __forceinline__ void cp_commit() {
    asm volatile("cp.async.commit_group;\n" ::: "memory");
}
__device__ __forceinline__ void cp_wait0() {
    asm volatile("cp.async.wait_group 0;\n" ::: "memory");
}

// ---------------- scratch (device globals; no allocation) ----------------
__device__ float g_act1[32  * BATCH * 208 * 208];
__device__ float g_act2[64  * BATCH * 104 * 104];
__device__ float g_act3[128 * BATCH * 52  * 52];
__device__ float g_act4[256 * BATCH * 26  * 26];
__device__ float g_act5[512 * BATCH * 13  * 13];
__device__ float g_feat1[255 * BATCH * 13 * 13];
__device__ float g_feat2[255 * BATCH * 26 * 26];
__device__ float g_col[25000000];   // im2col scratch + split-K partials @ +10M
__device__ float g_cand[BATCH * NCAND * 8];

#define PARTIAL_OFF 10000000

// ---------------- im2col: in -> col[K9][BATCH*P] ----------------
template <int CIN, int HIN, int WIN, int HOUT, int WOUT, bool NCHW>
__global__ void im2col_kernel(const float* __restrict__ in, float* __restrict__ col)
{
    constexpr int P = HOUT * WOUT;
    constexpr int NN = BATCH * P;
    constexpr int HWIN = HIN * WIN;
    const int k = blockIdx.y;
    const int n = blockIdx.x * 256 + threadIdx.x;
    if (n >= NN) return;
    const int c  = k / 9;
    const int t  = k - 9 * c;
    const int ky = t / 3;
    const int kx = t - 3 * ky;
    const int b  = n / P;
    const int p  = n - b * P;
    const int oy = p / WOUT;
    const int ox = p - oy * WOUT;
    const int iy = 2 * oy + ky;
    const int ix = 2 * ox + kx;
    float v = 0.f;
    if (iy < HIN && ix < WIN) {
        v = NCHW ? in[((size_t)(b * CIN + c) * HIN + iy) * WIN + ix]
                 : in[(size_t)(c * BATCH + b) * HWIN + iy * WIN + ix];
    }
    col[(size_t)k * NN + n] = v;
}

// ---------------- small-M GEMM for L1 (K=27, M=32) ----------------
template <int M, int N, int K, int BM, int BN, int TM, bool LRELU>
__global__ void __launch_bounds__(256)
gemm_kernel(const float* __restrict__ A, const float* __restrict__ B,
            const float* __restrict__ bias, float* __restrict__ C)
{
    constexpr int BK = 16;
    constexpr int TX = BN / 8;
    constexpr int TY = BM / TM;
    static_assert(TX * TY == 256, "thread count");
    constexpr int NB4 = BN / 4;

    __shared__ __align__(16) float  As[BK][BM + 4];
    __shared__ __align__(16) float4 Bs4[BK][NB4];

    const int tid = threadIdx.x;
    const int tx  = tid % TX;
    const int ty  = tid / TX;
    const int m0  = blockIdx.y * BM;
    const int n0  = blockIdx.x * BN;

    u64 acc[TM][4];
    #pragma unroll
    for (int i = 0; i < TM; i++)
        #pragma unroll
        for (int j = 0; j < 4; j++) acc[i][j] = pack2(0.f, 0.f);

    for (int kt = 0; kt < K; kt += BK) {
        #pragma unroll
        for (int i = tid; i < BM * BK; i += 256) {
            int m  = i >> 4;
            int kk = i & 15;
            float v = 0.f;
            bool ok = true;
            if (M % BM != 0) ok = (m0 + m) < M;
            if (K % BK != 0) ok = ok && (kt + kk) < K;
            if (ok) v = A[(size_t)(m0 + m) * K + kt + kk];
            As[kk][m] = v;
        }
        #pragma unroll
        for (int i = tid; i < BK * NB4; i += 256) {
            int kk = i / NB4;
            int n4 = i - kk * NB4;
            int gn = n0 + n4 * 4;
            float4 v = make_float4(0.f, 0.f, 0.f, 0.f);
            bool ok = true;
            if (K % BK != 0) ok = (kt + kk) < K;
            if (N % BN != 0) ok = ok && (gn < N);
            if (ok) v = *reinterpret_cast<const float4*>(&B[(size_t)(kt + kk) * N + gn]);
            Bs4[kk][n4] = v;
        }
        __syncthreads();

        #pragma unroll
        for (int kk = 0; kk < BK; kk++) {
            float4 bfa = Bs4[kk][tx];
            float4 bfb = Bs4[kk][NB4 / 2 + tx];
            u64 b01 = pack2(bfa.x, bfa.y);
            u64 b23 = pack2(bfa.z, bfa.w);
            u64 b45 = pack2(bfb.x, bfb.y);
            u64 b67 = pack2(bfb.z, bfb.w);
            float av[TM];
            float2 a2 = *reinterpret_cast<const float2*>(&As[kk][ty * 2]);
            av[0] = a2.x; av[1] = a2.y;
            #pragma unroll
            for (int i = 0; i < TM; i++) {
                u64 a2p = pack2(av[i], av[i]);
                acc[i][0] = fma2(a2p, b01, acc[i][0]);
                acc[i][1] = fma2(a2p, b23, acc[i][1]);
                acc[i][2] = fma2(a2p, b45, acc[i][2]);
                acc[i][3] = fma2(a2p, b67, acc[i][3]);
            }
        }
        __syncthreads();
    }

    #pragma unroll
    for (int i = 0; i < TM; i++) {
        int m = m0 + ty * TM + i;
        if (M % BM != 0 && m >= M) continue;
        float bb = bias[m];
        float x0, x1, x2, x3;
        int gn = n0 + tx * 4;
        if (N % BN == 0 || gn < N) {
            unpack2(acc[i][0], x0, x1);
            unpack2(acc[i][1], x2, x3);
            x0 += bb; x1 += bb; x2 += bb; x3 += bb;
            if (LRELU) {
                x0 = x0 > 0.f ? x0 : 0.1f * x0;
                x1 = x1 > 0.f ? x1 : 0.1f * x1;
                x2 = x2 > 0.f ? x2 : 0.1f * x2;
                x3 = x3 > 0.f ? x3 : 0.1f * x3;
            }
            *reinterpret_cast<float4*>(&C[(size_t)m * N + gn]) = make_float4(x0, x1, x2, x3);
        }
        int gn2 = n0 + BN / 2 + tx * 4;
        if (N % BN == 0 || gn2 < N) {
            unpack2(acc[i][2], x0, x1);
            unpack2(acc[i][3], x2, x3);
            x0 += bb; x1 += bb; x2 += bb; x3 += bb;
            if (LRELU) {
                x0 = x0 > 0.f ? x0 : 0.1f * x0;
                x1 = x1 > 0.f ? x1 : 0.1f * x1;
                x2 = x2 > 0.f ? x2 : 0.1f * x2;
                x3 = x3 > 0.f ? x3 : 0.1f * x3;
            }
            *reinterpret_cast<float4*>(&C[(size_t)m * N + gn2]) = make_float4(x0, x1, x2, x3);
        }
    }
}

// ---------------- main GEMM: 8x8 tile, cp.async B, smem double-buffer ------
// C[M][N] = A[M][K]*B[K][N]; SK>1 -> partials (no bias) at C[sk][M][N].
template <int M, int N, int K, int BM, int BN, int SK, int THREADS, bool LRELU>
__global__ void __launch_bounds__(THREADS, (THREADS == 128 ? 4 : 2))
gemm9_kernel(const float* __restrict__ A, const float* __restrict__ B,
             const float* __restrict__ bias, float* __restrict__ C)
{
    constexpr int BK = 16;
    constexpr int TX = BN / 8;
    constexpr int TY = BM / 8;
    static_assert(TX * TY == THREADS, "threads");
    constexpr int KC = K / SK;
    static_assert(KC % BK == 0, "K chunk must be multiple of BK");
    static_assert(N % 4 == 0, "N align");
    constexpr int NB4 = BN / 4;
    constexpr int AE  = BM * BK / THREADS;   // scalar A floats per thread
    constexpr int BE4 = BK * NB4 / THREADS;  // float4 B per thread

    __shared__ __align__(16) float  As[2][BK][BM + 4];
    __shared__ __align__(16) float4 Bs[2][BK][NB4];

    const int tid = threadIdx.x;
    const int tx  = tid % TX;
    const int ty  = tid / TX;
    const int m0  = blockIdx.y * BM;
    const int n0  = blockIdx.x * BN;
    const int k00 = blockIdx.z * KC;

    float ar[AE];

    u64 acc[8][4];
    #pragma unroll
    for (int i = 0; i < 8; i++)
        #pragma unroll
        for (int j = 0; j < 4; j++) acc[i][j] = pack2(0.f, 0.f);

    // ---- prologue: stage 0
    #pragma unroll
    for (int j = 0; j < BE4; j++) {
        int i = tid + j * THREADS;
        int kk = i / NB4, n4 = i % NB4;
        int gn = n0 + n4 * 4;
        bool ok = (N % BN == 0) || (gn < N);
        const float* src = ok ? &B[(size_t)(k00 + kk) * N + gn] : B;
        cp_async16(smem_u32(&Bs[0][kk][n4]), src, ok);
    }
    cp_commit();
    #pragma unroll
    for (int j = 0; j < AE; j++) {
        int i = tid + j * THREADS;
        int kk = i % BK, m = i / BK;
        float v = 0.f;
        if (M % BM == 0 || (m0 + m) < M) v = A[(size_t)(m0 + m) * K + k00 + kk];
        ar[j] = v;
    }
    #pragma unroll
    for (int j = 0; j < AE; j++) {
        int i = tid + j * THREADS;
        As[0][i % BK][i / BK] = ar[j];
    }
    cp_wait0();
    __syncthreads();

    int buf = 0;
    for (int kt = 0; kt < KC; kt += BK) {
        const bool has_next = (kt + BK) < KC;
        if (has_next) {
            #pragma unroll
            for (int j = 0; j < BE4; j++) {
                int i = tid + j * THREADS;
                int kk = i / NB4, n4 = i % NB4;
                int gn = n0 + n4 * 4;
                bool ok = (N % BN == 0) || (gn < N);
                const float* src = ok ? &B[(size_t)(k00 + kt + BK + kk) * N + gn] : B;
                cp_async16(smem_u32(&Bs[buf ^ 1][kk][n4]), src, ok);
            }
            cp_commit();
            #pragma unroll
            for (int j = 0; j < AE; j++) {
                int i = tid + j * THREADS;
                int kk = i % BK, m = i / BK;
                float v = 0.f;
                if (M % BM == 0 || (m0 + m) < M)
                    v = A[(size_t)(m0 + m) * K + k00 + kt + BK + kk];
                ar[j] = v;
            }
        }

        #pragma unroll
        for (int kk = 0; kk < BK; kk++) {
            float4 a0 = *reinterpret_cast<const float4*>(&As[buf][kk][ty * 8]);
            float4 a1 = *reinterpret_cast<const float4*>(&As[buf][kk][ty * 8 + 4]);
            float4 bA = Bs[buf][kk][tx * 2];
            float4 bB = Bs[buf][kk][tx * 2 + 1];
            u64 b01 = pack2(bA.x, bA.y);
            u64 b23 = pack2(bA.z, bA.w);
            u64 b45 = pack2(bB.x, bB.y);
            u64 b67 = pack2(bB.z, bB.w);
            float av[8] = {a0.x, a0.y, a0.z, a0.w, a1.x, a1.y, a1.z, a1.w};
            #pragma unroll
            for (int i = 0; i < 8; i++) {
                u64 ap = pack2(av[i], av[i]);
                acc[i][0] = fma2(ap, b01, acc[i][0]);
                acc[i][1] = fma2(ap, b23, acc[i][1]);
                acc[i][2] = fma2(ap, b45, acc[i][2]);
                acc[i][3] = fma2(ap, b67, acc[i][3]);
            }
        }

        if (has_next) {
            #pragma unroll
            for (int j = 0; j < AE; j++) {
                int i = tid + j * THREADS;
                As[buf ^ 1][i % BK][i / BK] = ar[j];
            }
            cp_wait0();
            __syncthreads();
            buf ^= 1;
        }
    }

    // ---- epilogue
    float* Cb = (SK == 1) ? C : (C + (size_t)blockIdx.z * M * N);
    #pragma unroll
    for (int i = 0; i < 8; i++) {
        int m = m0 + ty * 8 + i;
        if (M % BM != 0 && m >= M) continue;
        int gn = n0 + tx * 8;
        if (N % BN != 0 && gn >= N) continue;
        float x0, x1, x2, x3, x4, x5, x6, x7;
        unpack2(acc[i][0], x0, x1);
        unpack2(acc[i][1], x2, x3);
        unpack2(acc[i][2], x4, x5);
        unpack2(acc[i][3], x6, x7);
        if (SK == 1) {
            float bb = bias[m];
            x0 += bb; x1 += bb; x2 += bb; x3 += bb;
            x4 += bb; x5 += bb; x6 += bb; x7 += bb;
            if (LRELU) {
                x0 = x0 > 0.f ? x0 : 0.1f * x0;
                x1 = x1 > 0.f ? x1 : 0.1f * x1;
                x2 = x2 > 0.f ? x2 : 0.1f * x2;
                x3 = x3 > 0.f ? x3 : 0.1f * x3;
                x4 = x4 > 0.f ? x4 : 0.1f * x4;
                x5 = x5 > 0.f ? x5 : 0.1f * x5;
                x6 = x6 > 0.f ? x6 : 0.1f * x6;
                x7 = x7 > 0.f ? x7 : 0.1f * x7;
            }
        }
        *reinterpret_cast<float4*>(&Cb[(size_t)m * N + gn])     = make_float4(x0, x1, x2, x3);
        *reinterpret_cast<float4*>(&Cb[(size_t)m * N + gn + 4]) = make_float4(x4, x5, x6, x7);
    }
}

// ---------------- split-K reduce: C = sum_sk part + bias (+lrelu) ----------
template <int M, int N, int SK, bool LRELU>
__global__ void reduce_kernel(const float* __restrict__ part,
                              const float* __restrict__ bias,
                              float* __restrict__ C)
{
    int i4 = (blockIdx.x * 256 + threadIdx.x) * 4;
    if (i4 >= M * N) return;
    float4 s = *reinterpret_cast<const float4*>(&part[i4]);
    #pragma unroll
    for (int sk = 1; sk < SK; sk++) {
        float4 p = *reinterpret_cast<const float4*>(&part[(size_t)sk * M * N + i4]);
        s.x += p.x; s.y += p.y; s.z += p.z; s.w += p.w;
    }
    float bb = bias[i4 / N];
    s.x += bb; s.y += bb; s.z += bb; s.w += bb;
    if (LRELU) {
        s.x = s.x > 0.f ? s.x : 0.1f * s.x;
        s.y = s.y > 0.f ? s.y : 0.1f * s.y;
        s.z = s.z > 0.f ? s.z : 0.1f * s.z;
        s.w = s.w > 0.f ? s.w : 0.1f * s.w;
    }
    *reinterpret_cast<float4*>(&C[i4]) = s;
}

// ---------------- decode: feat (CNHW) -> candidate record ----------------
__device__ __forceinline__ float sigmoidf_(float x) { return 1.f / (1.f + expf(-x)); }

__global__ void decode_kernel(const float* __restrict__ feat1,
                              const float* __restrict__ feat2,
                              float* __restrict__ cand)
{
    int idx = blockIdx.x * blockDim.x + threadIdx.x;
    if (idx >= BATCH * NCAND) return;
    int b = idx / NCAND;
    int n = idx - b * NCAND;

    const float A1w[3] = {81.f, 135.f, 344.f}, A1h[3] = {82.f, 169.f, 319.f};
    const float A2w[3] = {10.f, 23.f,  37.f},  A2h[3] = {14.f, 27.f,  58.f};

    const float* base;
    int H, W, a, yy, xx;
    size_t estr;
    float aw, ah;
    if (n < 507) {
        H = 13; W = 13;
        a = n / 169; int r = n - a * 169; yy = r / 13; xx = r - yy * 13;
        aw = A1w[a]; ah = A1h[a];
        estr = (size_t)BATCH * 169;
        base = feat1 + (size_t)(a * 85) * estr + b * 169 + yy * 13 + xx;
    } else {
        int m = n - 507;
        H = 26; W = 26;
        a = m / 676; int r = m - a * 676; yy = r / 26; xx = r - yy * 26;
        aw = A2w[a]; ah = A2h[a];
        estr = (size_t)BATCH * 676;
        base = feat2 + (size_t)(a * 85) * estr + b * 676 + yy * 26 + xx;
    }

    float t0 = base[0];
    float t1 = base[estr];
    float t2 = base[2 * estr];
    float t3 = base[3 * estr];
    float t4 = base[4 * estr];

    float bx = (sigmoidf_(t0) + (float)xx) / (float)W;
    float by = (sigmoidf_(t1) + (float)yy) / (float)H;
    float bw = expf(t2) * aw / 416.f;
    float bh = expf(t3) * ah / 416.f;
    float obj = sigmoidf_(t4);

    float ml = base[5 * estr];
    int lab = 0;
    for (int c = 1; c < 80; c++) {
        float v = base[(5 + c) * estr];
        if (v > ml) { ml = v; lab = c; }
    }
    float cc = sigmoidf_(ml);
    float score = obj * cc;
    if (!(score >= 0.1f)) score = 0.f;

    float* o = cand + (size_t)idx * 8;
    o[0] = (by - bh * 0.5f) * 416.f;
    o[1] = (bx - bw * 0.5f) * 416.f;
    o[2] = (by + bh * 0.5f) * 416.f;
    o[3] = (bx + bw * 0.5f) * 416.f;
    o[4] = obj;
    o[5] = cc;
    o[6] = (float)lab;
    o[7] = score;
}

// ---------------- per-image top-k (bitonic) + greedy NMS ----------------
__global__ void nms_kernel(const float* __restrict__ cand, float* __restrict__ out)
{
    const int b = blockIdx.x;
    const int tid = threadIdx.x; // 512 threads

    __shared__ u64 keys[NPAD];

    const float* cb = cand + (size_t)b * NCAND * 8;

    // key = (score_bits << 32) | (~idx): sort desc == score desc, idx asc
    for (int i = tid; i < NPAD; i += 512) {
        u64 k = 0;
        if (i < NCAND) {
            float sc = cb[i * 8 + 7];       // >= 0 by construction
            k = ((u64)__float_as_uint(sc) << 32) | (u64)(0xFFFFFFFFu - (unsigned)i);
        }
        keys[i] = k;
    }
    __syncthreads();

    // bitonic sort, descending
    for (int k = 2; k <= NPAD; k <<= 1) {
        for (int j = k >> 1; j > 0; j >>= 1) {
            for (int t = tid; t < NPAD / 2; t += 512) {
                int i = ((t / j) * (j << 1)) + (t % j);
                int l = i + j;
                u64 a = keys[i], c = keys[l];
                bool desc = ((i & k) == 0);
                if (desc ? (a < c) : (a > c)) { keys[i] = c; keys[l] = a; }
            }
            __syncthreads();
        }
    }

    // load selected boxes
    __shared__ float y0s[TOPK], x0s[TOPK], y1s[TOPK], x1s[TOPK], areas[TOPK];
    __shared__ int labs[TOPK];
    __shared__ int sel[TOPK];
    __shared__ unsigned char keep[TOPK];
    if (tid < TOPK) {
        u64 k = keys[tid];
        int ii = (int)(0xFFFFFFFFu - (unsigned)(k & 0xFFFFFFFFu));
        sel[tid] = ii;
        float y0 = cb[ii * 8 + 0], x0 = cb[ii * 8 + 1];
        float y1 = cb[ii * 8 + 2], x1 = cb[ii * 8 + 3];
        y0s[tid] = y0; x0s[tid] = x0; y1s[tid] = y1; x1s[tid] = x1;
        areas[tid] = (y1 - y0) * (x1 - x0);
        labs[tid] = (int)cb[ii * 8 + 6];
        keep[tid] = ((unsigned)(k >> 32) != 0u) ? 1 : 0;  // score > 0
    }
    __syncthreads();

    // sequential greedy suppression (matches the fori_loop semantics)
    for (int j = 0; j < TOPK - 1; j++) {
        if (tid > j && tid < TOPK && keep[j] && keep[tid] && labs[tid] == labs[j]) {
            float ty0 = fmaxf(y0s[tid], y0s[j]);
            float tx0 = fmaxf(x0s[tid], x0s[j]);
            float ty1 = fminf(y1s[tid], y1s[j]);
            float tx1 = fminf(x1s[tid], x1s[j]);
            float ih = fmaxf(ty1 - ty0, 0.f);
            float iw = fmaxf(tx1 - tx0, 0.f);
            float inter = ih * iw;
            float iou = inter / (areas[tid] + areas[j] - inter + 1e-9f);
            if (iou > 0.5f) keep[tid] = 0;
        }
        __syncthreads();
    }

    if (tid < TOPK) {
        float* o = out + ((size_t)b * TOPK + tid) * 7;
        if (keep[tid]) {
            int ii = sel[tid];
            o[0] = y0s[tid]; o[1] = x0s[tid]; o[2] = y1s[tid]; o[3] = x1s[tid];
            o[4] = cb[ii * 8 + 4];
            o[5] = cb[ii * 8 + 5];
            o[6] = (float)labs[tid];
        } else {
            #pragma unroll
            for (int k = 0; k < 7; k++) o[k] = 0.f;
        }
    }
}

// ---------------- launch ----------------
static inline int ceil_div(int a, int b) { return (a + b - 1) / b; }

extern "C" void kernel_launch(void* const* d_in, const int* in_sizes, int n_in,
                              void* d_out, int out_size)
{
    (void)in_sizes; (void)n_in; (void)out_size;
    const float* images = (const float*)d_in[0];
    const float* w1 = (const float*)d_in[1];  const float* b1 = (const float*)d_in[2];
    const float* w2 = (const float*)d_in[3];  const float* b2 = (const float*)d_in[4];
    const float* w3 = (const float*)d_in[5];  const float* b3 = (const float*)d_in[6];
    const float* w4 = (const float*)d_in[7];  const float* b4 = (const float*)d_in[8];
    const float* w5 = (const float*)d_in[9];  const float* b5 = (const float*)d_in[10];
    const float* wh1 = (const float*)d_in[11]; const float* bh1 = (const float*)d_in[12];
    const float* wh2 = (const float*)d_in[13]; const float* bh2 = (const float*)d_in[14];
    float* out = (float*)d_out;

    static float *act1 = nullptr, *act2, *act3, *act4, *act5, *feat1, *feat2, *col, *cand;
    if (!act1) {
        cudaGetSymbolAddress((void**)&act1, g_act1);
        cudaGetSymbolAddress((void**)&act2, g_act2);
        cudaGetSymbolAddress((void**)&act3, g_act3);
        cudaGetSymbolAddress((void**)&act4, g_act4);
        cudaGetSymbolAddress((void**)&act5, g_act5);
        cudaGetSymbolAddress((void**)&feat1, g_feat1);
        cudaGetSymbolAddress((void**)&feat2, g_feat2);
        cudaGetSymbolAddress((void**)&col,  g_col);
        cudaGetSymbolAddress((void**)&cand, g_cand);
    }
    float* part = col + PARTIAL_OFF;

    // --- L1: 3->32, 416->208  (N = 346112, K = 27)
    im2col_kernel<3, 416, 416, 208, 208, true>
        <<<dim3(ceil_div(346112, 256), 27), 256>>>(images, col);
    gemm_kernel<32, 346112, 27, 32, 128, 2, true>
        <<<dim3(346112 / 128, 1), 256>>>(w1, col, b1, act1);

    // --- L2: 32->64, 208->104 (N = 86528, K = 288), M=64 -> BM=64
    im2col_kernel<32, 208, 208, 104, 104, false>
        <<<dim3(ceil_div(86528, 256), 288), 256>>>(act1, col);
    gemm9_kernel<64, 86528, 288, 64, 128, 1, 128, true>
        <<<dim3(86528 / 128, 1, 1), 128>>>(w2, col, b2, act2);

    // --- L3: 64->128, 104->52 (N = 21632, K = 576), BM=128
    im2col_kernel<64, 104, 104, 52, 52, false>
        <<<dim3(ceil_div(21632, 256), 576), 256>>>(act2, col);
    gemm9_kernel<128, 21632, 576, 128, 128, 1, 256, true>
        <<<dim3(21632 / 128, 1, 1), 256>>>(w3, col, b3, act3);

    // --- L4: 128->256, 52->26 (N = 5408, K = 1152), BM=128, split-K 2
    im2col_kernel<128, 52, 52, 26, 26, false>
        <<<dim3(ceil_div(5408, 256), 1152), 256>>>(act3, col);
    gemm9_kernel<256, 5408, 1152, 128, 128, 2, 256, false>
        <<<dim3(ceil_div(5408, 128), 2, 2), 256>>>(w4, col, b4, part);
    reduce_kernel<256, 5408, 2, true>
        <<<ceil_div(256 * 5408 / 4, 256), 256>>>(part, b4, act4);

    // --- head2: 255 x 5408, K = 256, BM=128, split-K 2
    gemm9_kernel<255, 5408, 256, 128, 128, 2, 256, false>
        <<<dim3(ceil_div(5408, 128), 2, 2), 256>>>(wh2, act4, bh2, part);
    reduce_kernel<255, 5408, 2, false>
        <<<ceil_div(255 * 5408 / 4 + 1, 256), 256>>>(part, bh2, feat2);

    // --- L5: 256->512, 26->13 (N = 1352, K = 2304), BM=128, split-K 4
    im2col_kernel<256, 26, 26, 13, 13, false>
        <<<dim3(ceil_div(1352, 256), 2304), 256>>>(act4, col);
    gemm9_kernel<512, 1352, 2304, 128, 128, 4, 256, false>
        <<<dim3(ceil_div(1352, 128), 4, 4), 256>>>(w5, col, b5, part);
    reduce_kernel<512, 1352, 4, true>
        <<<ceil_div(512 * 1352 / 4, 256), 256>>>(part, b5, act5);

    // --- head1: 255 x 1352, K = 512, BM=128, split-K 4
    gemm9_kernel<255, 1352, 512, 128, 128, 4, 256, false>
        <<<dim3(ceil_div(1352, 128), 2, 4), 256>>>(wh1, act5, bh1, part);
    reduce_kernel<255, 1352, 4, false>
        <<<ceil_div(255 * 1352 / 4 + 1, 256), 256>>>(part, bh1, feat1);

    // --- decode + nms
    decode_kernel<<<ceil_div(BATCH * NCAND, 256), 256>>>(feat1, feat2, cand);
    nms_kernel<<<BATCH, 512>>>(cand, out);
}

// round 9
// speedup vs baseline: 2.1973x; 1.1695x over previous
#include <cuda_runtime.h>
#include <cstdint>

#define BATCH 8
#define NCAND 2535   // 3*13*13 + 3*26*26
#define TOPK 300
#define NPAD 4096

typedef unsigned long long u64;

__device__ __forceinline__ u64 pack2(float x, float y) {
    u64 r;
    asm("mov.b64 %0, {%1, %2};" : "=l"(r)
        : "r"(__float_as_uint(x)), "r"(__float_as_uint(y)));
    return r;
}
__device__ __forceinline__ void unpack2(u64 v, float& x, float& y) {
    unsigned a, b;
    asm("mov.b64 {%0, %1}, %2;" : "=r"(a), "=r"(b) : "l"(v));
    x = __uint_as_float(a); y = __uint_as_float(b);
}
__device__ __forceinline__ u64 fma2(u64 a, u64 b, u64 c) {
    u64 d;
    asm("fma.rn.f32x2 %0, %1, %2, %3;" : "=l"(d) : "l"(a), "l"(b), "l"(c));
    return d;
}
__device__ __forceinline__ unsigned smem_u32(const void* p) {
    return (unsigned)__cvta_generic_to_shared(p);
}
__device__ __forceinline__ void cp_async16(unsigned dst, const void* src, bool valid) {
    int sz = valid ? 16 : 0;
    asm volatile("cp.async.ca.shared.global [%0], [%1], 16, %2;\n"
                 :: "r"(dst), "l"(src), "r"(sz) : "memory");
}
__device__ __forceinline__ void cp_commit() {
    asm volatile("cp.async.commit_group;\n" ::: "memory");
}
__device__ __forceinline__ void cp_wait0() {
    asm volatile("cp.async.wait_group 0;\n" ::: "memory");
}

// ---------------- scratch (device globals; no allocation) ----------------
__device__ float g_act1[32  * BATCH * 208 * 208];
__device__ float g_act2[64  * BATCH * 104 * 104];
__device__ float g_act3[128 * BATCH * 52  * 52];
__device__ float g_act4[256 * BATCH * 26  * 26];
__device__ float g_act5[512 * BATCH * 13  * 13];
__device__ float g_feat1[255 * BATCH * 13 * 13];
__device__ float g_feat2[255 * BATCH * 26 * 26];
__device__ float g_part[4 * 512 * 5408];          // split-K partials (max 4*255*5408 / 4*512*1352)
__device__ float g_cand[BATCH * NCAND * 8];

// ---------------- fused im2col GEMM: 3x3 stride-2 conv as implicit GEMM ----
// C[M][N] = W[M][K] * im2col(act)[K][N], K = CIN*9, N = BATCH*HOUT*WOUT.
// BM=64, BN=128, BK=16, 128 threads, 8x8 f32x2 micro-tile.
// Thread t owns output column n0+t for B staging: (b,oy,ox) computed once.
// act layout: NCHW ? [B][CIN][HIN][WIN] : [CIN][BATCH][HIN][WIN].
// SK>1 -> partials (no bias) at C[sk][M][N].
template <int M, int N, int K, int SK, bool LRELU, bool NCHW,
          int CIN, int HIN, int WIN, int HOUT, int WOUT>
__global__ void __launch_bounds__(128, 3)
gemm9f_kernel(const float* __restrict__ A, const float* __restrict__ act,
              const float* __restrict__ bias, float* __restrict__ C)
{
    constexpr int BM = 64, BN = 128, BK = 16, THREADS = 128;
    constexpr int TX = BN / 8;   // 16
    constexpr int KC = (K % SK == 0) ? (K / SK) : K;  // K chunk per z (SK>1 requires K%SK==0)
    constexpr int NT = (KC + BK - 1) / BK;            // tiles
    constexpr int P = HOUT * WOUT;
    constexpr int HWIN = HIN * WIN;
    constexpr int AE = BM * BK / THREADS;             // 8 scalar A per thread
    constexpr size_t CSTR = NCHW ? (size_t)HWIN : (size_t)BATCH * HWIN;

    __shared__ __align__(16) float As[2][BK][BM + 4];
    __shared__ __align__(16) float Bs[2][BK][BN];

    const int tid = threadIdx.x;
    const int tx  = tid % TX;
    const int ty  = tid / TX;
    const int m0  = blockIdx.y * BM;
    const int n0  = blockIdx.x * BN;
    const int k00 = blockIdx.z * KC;

    // per-thread B column decomposition (fixed for whole kernel)
    const int gn = n0 + tid;
    const bool n_ok = (N % BN == 0) || (gn < N);
    const int gsafe = n_ok ? gn : 0;
    const int bb = gsafe / P;
    const int pp = gsafe - bb * P;
    const int oy = pp / WOUT;
    const int ox = pp - oy * WOUT;
    const int iy0 = 2 * oy;
    const int ix0 = 2 * ox;
    const size_t base_b = (NCHW ? (size_t)bb * CIN : (size_t)bb) * HWIN;

    float ar[AE];
    float br[BK];

    u64 acc[8][4];
    #pragma unroll
    for (int i = 0; i < 8; i++)
        #pragma unroll
        for (int j = 0; j < 4; j++) acc[i][j] = pack2(0.f, 0.f);

    // gather helpers
    auto gatherB = [&](int kt) {
        #pragma unroll
        for (int j = 0; j < BK; j++) {
            int kl = kt + j;
            int kg = k00 + kl;
            int c  = kg / 9;
            int t  = kg - 9 * c;
            int ky = t / 3;
            int kx = t - 3 * ky;
            int iy = iy0 + ky;
            int ix = ix0 + kx;
            bool ok = n_ok && (iy < HIN) && (ix < WIN);
            if (KC % BK != 0) ok = ok && (kl < KC);
            br[j] = ok ? __ldg(act + base_b + (size_t)c * CSTR + iy * WIN + ix) : 0.f;
        }
    };
    auto gatherA = [&](int kt) {
        #pragma unroll
        for (int j = 0; j < AE; j++) {
            int i = tid + j * THREADS;
            int m = i >> 4, kk = i & 15;
            bool ok = true;
            if (M % BM != 0) ok = (m0 + m) < M;
            if (KC % BK != 0) ok = ok && ((kt + kk) < KC);
            ar[j] = ok ? A[(size_t)(m0 + m) * K + k00 + kt + kk] : 0.f;
        }
    };

    // prologue: tile 0
    gatherB(0);
    gatherA(0);
    #pragma unroll
    for (int j = 0; j < BK; j++) Bs[0][j][tid] = br[j];
    #pragma unroll
    for (int j = 0; j < AE; j++) {
        int i = tid + j * THREADS;
        As[0][i & 15][i >> 4] = ar[j];
    }
    __syncthreads();

    int buf = 0;
    for (int tt = 0; tt < NT; tt++) {
        const bool has_next = (tt + 1) < NT;
        if (has_next) {
            gatherB((tt + 1) * BK);
            gatherA((tt + 1) * BK);
        }

        #pragma unroll
        for (int kk = 0; kk < BK; kk++) {
            float4 a0 = *reinterpret_cast<const float4*>(&As[buf][kk][ty * 8]);
            float4 a1 = *reinterpret_cast<const float4*>(&As[buf][kk][ty * 8 + 4]);
            float4 bA = *reinterpret_cast<const float4*>(&Bs[buf][kk][tx * 8]);
            float4 bB = *reinterpret_cast<const float4*>(&Bs[buf][kk][tx * 8 + 4]);
            u64 b01 = pack2(bA.x, bA.y);
            u64 b23 = pack2(bA.z, bA.w);
            u64 b45 = pack2(bB.x, bB.y);
            u64 b67 = pack2(bB.z, bB.w);
            float av[8] = {a0.x, a0.y, a0.z, a0.w, a1.x, a1.y, a1.z, a1.w};
            #pragma unroll
            for (int i = 0; i < 8; i++) {
                u64 ap = pack2(av[i], av[i]);
                acc[i][0] = fma2(ap, b01, acc[i][0]);
                acc[i][1] = fma2(ap, b23, acc[i][1]);
                acc[i][2] = fma2(ap, b45, acc[i][2]);
                acc[i][3] = fma2(ap, b67, acc[i][3]);
            }
        }

        if (has_next) {
            #pragma unroll
            for (int j = 0; j < BK; j++) Bs[buf ^ 1][j][tid] = br[j];
            #pragma unroll
            for (int j = 0; j < AE; j++) {
                int i = tid + j * THREADS;
                As[buf ^ 1][i & 15][i >> 4] = ar[j];
            }
            __syncthreads();
            buf ^= 1;
        }
    }

    // epilogue
    float* Cb = (SK == 1) ? C : (C + (size_t)blockIdx.z * M * N);
    #pragma unroll
    for (int i = 0; i < 8; i++) {
        int m = m0 + ty * 8 + i;
        if (M % BM != 0 && m >= M) continue;
        int go = n0 + tx * 8;
        if (N % BN != 0 && go >= N) continue;
        float x0, x1, x2, x3, x4, x5, x6, x7;
        unpack2(acc[i][0], x0, x1);
        unpack2(acc[i][1], x2, x3);
        unpack2(acc[i][2], x4, x5);
        unpack2(acc[i][3], x6, x7);
        if (SK == 1) {
            float bbv = bias[m];
            x0 += bbv; x1 += bbv; x2 += bbv; x3 += bbv;
            x4 += bbv; x5 += bbv; x6 += bbv; x7 += bbv;
            if (LRELU) {
                x0 = x0 > 0.f ? x0 : 0.1f * x0;
                x1 = x1 > 0.f ? x1 : 0.1f * x1;
                x2 = x2 > 0.f ? x2 : 0.1f * x2;
                x3 = x3 > 0.f ? x3 : 0.1f * x3;
                x4 = x4 > 0.f ? x4 : 0.1f * x4;
                x5 = x5 > 0.f ? x5 : 0.1f * x5;
                x6 = x6 > 0.f ? x6 : 0.1f * x6;
                x7 = x7 > 0.f ? x7 : 0.1f * x7;
            }
        }
        *reinterpret_cast<float4*>(&Cb[(size_t)m * N + go])     = make_float4(x0, x1, x2, x3);
        *reinterpret_cast<float4*>(&Cb[(size_t)m * N + go + 4]) = make_float4(x4, x5, x6, x7);
    }
}

// ---------------- plain GEMM (heads): 8x8 tile, cp.async B, double-buffer --
template <int M, int N, int K, int BM, int BN, int SK, int THREADS, bool LRELU>
__global__ void __launch_bounds__(THREADS, (THREADS == 128 ? 4 : 2))
gemm9_kernel(const float* __restrict__ A, const float* __restrict__ B,
             const float* __restrict__ bias, float* __restrict__ C)
{
    constexpr int BK = 16;
    constexpr int TX = BN / 8;
    constexpr int TY = BM / 8;
    static_assert(TX * TY == THREADS, "threads");
    constexpr int KC = K / SK;
    static_assert(KC % BK == 0, "K chunk must be multiple of BK");
    static_assert(N % 4 == 0, "N align");
    constexpr int NB4 = BN / 4;
    constexpr int AE  = BM * BK / THREADS;
    constexpr int BE4 = BK * NB4 / THREADS;

    __shared__ __align__(16) float  As[2][BK][BM + 4];
    __shared__ __align__(16) float4 Bs[2][BK][NB4];

    const int tid = threadIdx.x;
    const int tx  = tid % TX;
    const int ty  = tid / TX;
    const int m0  = blockIdx.y * BM;
    const int n0  = blockIdx.x * BN;
    const int k00 = blockIdx.z * KC;

    float ar[AE];

    u64 acc[8][4];
    #pragma unroll
    for (int i = 0; i < 8; i++)
        #pragma unroll
        for (int j = 0; j < 4; j++) acc[i][j] = pack2(0.f, 0.f);

    #pragma unroll
    for (int j = 0; j < BE4; j++) {
        int i = tid + j * THREADS;
        int kk = i / NB4, n4 = i % NB4;
        int gn = n0 + n4 * 4;
        bool ok = (N % BN == 0) || (gn < N);
        const float* src = ok ? &B[(size_t)(k00 + kk) * N + gn] : B;
        cp_async16(smem_u32(&Bs[0][kk][n4]), src, ok);
    }
    cp_commit();
    #pragma unroll
    for (int j = 0; j < AE; j++) {
        int i = tid + j * THREADS;
        int kk = i % BK, m = i / BK;
        float v = 0.f;
        if (M % BM == 0 || (m0 + m) < M) v = A[(size_t)(m0 + m) * K + k00 + kk];
        ar[j] = v;
    }
    #pragma unroll
    for (int j = 0; j < AE; j++) {
        int i = tid + j * THREADS;
        As[0][i % BK][i / BK] = ar[j];
    }
    cp_wait0();
    __syncthreads();

    int buf = 0;
    for (int kt = 0; kt < KC; kt += BK) {
        const bool has_next = (kt + BK) < KC;
        if (has_next) {
            #pragma unroll
            for (int j = 0; j < BE4; j++) {
                int i = tid + j * THREADS;
                int kk = i / NB4, n4 = i % NB4;
                int gn = n0 + n4 * 4;
                bool ok = (N % BN == 0) || (gn < N);
                const float* src = ok ? &B[(size_t)(k00 + kt + BK + kk) * N + gn] : B;
                cp_async16(smem_u32(&Bs[buf ^ 1][kk][n4]), src, ok);
            }
            cp_commit();
            #pragma unroll
            for (int j = 0; j < AE; j++) {
                int i = tid + j * THREADS;
                int kk = i % BK, m = i / BK;
                float v = 0.f;
                if (M % BM == 0 || (m0 + m) < M)
                    v = A[(size_t)(m0 + m) * K + k00 + kt + BK + kk];
                ar[j] = v;
            }
        }

        #pragma unroll
        for (int kk = 0; kk < BK; kk++) {
            float4 a0 = *reinterpret_cast<const float4*>(&As[buf][kk][ty * 8]);
            float4 a1 = *reinterpret_cast<const float4*>(&As[buf][kk][ty * 8 + 4]);
            float4 bA = Bs[buf][kk][tx * 2];
            float4 bB = Bs[buf][kk][tx * 2 + 1];
            u64 b01 = pack2(bA.x, bA.y);
            u64 b23 = pack2(bA.z, bA.w);
            u64 b45 = pack2(bB.x, bB.y);
            u64 b67 = pack2(bB.z, bB.w);
            float av[8] = {a0.x, a0.y, a0.z, a0.w, a1.x, a1.y, a1.z, a1.w};
            #pragma unroll
            for (int i = 0; i < 8; i++) {
                u64 ap = pack2(av[i], av[i]);
                acc[i][0] = fma2(ap, b01, acc[i][0]);
                acc[i][1] = fma2(ap, b23, acc[i][1]);
                acc[i][2] = fma2(ap, b45, acc[i][2]);
                acc[i][3] = fma2(ap, b67, acc[i][3]);
            }
        }

        if (has_next) {
            #pragma unroll
            for (int j = 0; j < AE; j++) {
                int i = tid + j * THREADS;
                As[buf ^ 1][i % BK][i / BK] = ar[j];
            }
            cp_wait0();
            __syncthreads();
            buf ^= 1;
        }
    }

    float* Cb = (SK == 1) ? C : (C + (size_t)blockIdx.z * M * N);
    #pragma unroll
    for (int i = 0; i < 8; i++) {
        int m = m0 + ty * 8 + i;
        if (M % BM != 0 && m >= M) continue;
        int gn = n0 + tx * 8;
        if (N % BN != 0 && gn >= N) continue;
        float x0, x1, x2, x3, x4, x5, x6, x7;
        unpack2(acc[i][0], x0, x1);
        unpack2(acc[i][1], x2, x3);
        unpack2(acc[i][2], x4, x5);
        unpack2(acc[i][3], x6, x7);
        if (SK == 1) {
            float bb = bias[m];
            x0 += bb; x1 += bb; x2 += bb; x3 += bb;
            x4 += bb; x5 += bb; x6 += bb; x7 += bb;
            if (LRELU) {
                x0 = x0 > 0.f ? x0 : 0.1f * x0;
                x1 = x1 > 0.f ? x1 : 0.1f * x1;
                x2 = x2 > 0.f ? x2 : 0.1f * x2;
                x3 = x3 > 0.f ? x3 : 0.1f * x3;
                x4 = x4 > 0.f ? x4 : 0.1f * x4;
                x5 = x5 > 0.f ? x5 : 0.1f * x5;
                x6 = x6 > 0.f ? x6 : 0.1f * x6;
                x7 = x7 > 0.f ? x7 : 0.1f * x7;
            }
        }
        *reinterpret_cast<float4*>(&Cb[(size_t)m * N + gn])     = make_float4(x0, x1, x2, x3);
        *reinterpret_cast<float4*>(&Cb[(size_t)m * N + gn + 4]) = make_float4(x4, x5, x6, x7);
    }
}

// ---------------- split-K reduce: C = sum_sk part + bias (+lrelu) ----------
template <int M, int N, int SK, bool LRELU>
__global__ void reduce_kernel(const float* __restrict__ part,
                              const float* __restrict__ bias,
                              float* __restrict__ C)
{
    int i4 = (blockIdx.x * 256 + threadIdx.x) * 4;
    if (i4 >= M * N) return;
    float4 s = *reinterpret_cast<const float4*>(&part[i4]);
    #pragma unroll
    for (int sk = 1; sk < SK; sk++) {
        float4 p = *reinterpret_cast<const float4*>(&part[(size_t)sk * M * N + i4]);
        s.x += p.x; s.y += p.y; s.z += p.z; s.w += p.w;
    }
    float bb = bias[i4 / N];
    s.x += bb; s.y += bb; s.z += bb; s.w += bb;
    if (LRELU) {
        s.x = s.x > 0.f ? s.x : 0.1f * s.x;
        s.y = s.y > 0.f ? s.y : 0.1f * s.y;
        s.z = s.z > 0.f ? s.z : 0.1f * s.z;
        s.w = s.w > 0.f ? s.w : 0.1f * s.w;
    }
    *reinterpret_cast<float4*>(&C[i4]) = s;
}

// ---------------- decode: feat (CNHW) -> candidate record ----------------
__device__ __forceinline__ float sigmoidf_(float x) { return 1.f / (1.f + expf(-x)); }

__global__ void decode_kernel(const float* __restrict__ feat1,
                              const float* __restrict__ feat2,
                              float* __restrict__ cand)
{
    int idx = blockIdx.x * blockDim.x + threadIdx.x;
    if (idx >= BATCH * NCAND) return;
    int b = idx / NCAND;
    int n = idx - b * NCAND;

    const float A1w[3] = {81.f, 135.f, 344.f}, A1h[3] = {82.f, 169.f, 319.f};
    const float A2w[3] = {10.f, 23.f,  37.f},  A2h[3] = {14.f, 27.f,  58.f};

    const float* base;
    int H, W, a, yy, xx;
    size_t estr;
    float aw, ah;
    if (n < 507) {
        H = 13; W = 13;
        a = n / 169; int r = n - a * 169; yy = r / 13; xx = r - yy * 13;
        aw = A1w[a]; ah = A1h[a];
        estr = (size_t)BATCH * 169;
        base = feat1 + (size_t)(a * 85) * estr + b * 169 + yy * 13 + xx;
    } else {
        int m = n - 507;
        H = 26; W = 26;
        a = m / 676; int r = m - a * 676; yy = r / 26; xx = r - yy * 26;
        aw = A2w[a]; ah = A2h[a];
        estr = (size_t)BATCH * 676;
        base = feat2 + (size_t)(a * 85) * estr + b * 676 + yy * 26 + xx;
    }

    float t0 = base[0];
    float t1 = base[estr];
    float t2 = base[2 * estr];
    float t3 = base[3 * estr];
    float t4 = base[4 * estr];

    float bx = (sigmoidf_(t0) + (float)xx) / (float)W;
    float by = (sigmoidf_(t1) + (float)yy) / (float)H;
    float bw = expf(t2) * aw / 416.f;
    float bh = expf(t3) * ah / 416.f;
    float obj = sigmoidf_(t4);

    float ml = base[5 * estr];
    int lab = 0;
    for (int c = 1; c < 80; c++) {
        float v = base[(5 + c) * estr];
        if (v > ml) { ml = v; lab = c; }
    }
    float cc = sigmoidf_(ml);
    float score = obj * cc;
    if (!(score >= 0.1f)) score = 0.f;

    float* o = cand + (size_t)idx * 8;
    o[0] = (by - bh * 0.5f) * 416.f;
    o[1] = (bx - bw * 0.5f) * 416.f;
    o[2] = (by + bh * 0.5f) * 416.f;
    o[3] = (bx + bw * 0.5f) * 416.f;
    o[4] = obj;
    o[5] = cc;
    o[6] = (float)lab;
    o[7] = score;
}

// ---------------- per-image top-k (bitonic) + greedy NMS ----------------
__global__ void nms_kernel(const float* __restrict__ cand, float* __restrict__ out)
{
    const int b = blockIdx.x;
    const int tid = threadIdx.x; // 512 threads

    __shared__ u64 keys[NPAD];

    const float* cb = cand + (size_t)b * NCAND * 8;

    for (int i = tid; i < NPAD; i += 512) {
        u64 k = 0;
        if (i < NCAND) {
            float sc = cb[i * 8 + 7];
            k = ((u64)__float_as_uint(sc) << 32) | (u64)(0xFFFFFFFFu - (unsigned)i);
        }
        keys[i] = k;
    }
    __syncthreads();

    for (int k = 2; k <= NPAD; k <<= 1) {
        for (int j = k >> 1; j > 0; j >>= 1) {
            for (int t = tid; t < NPAD / 2; t += 512) {
                int i = ((t / j) * (j << 1)) + (t % j);
                int l = i + j;
                u64 a = keys[i], c = keys[l];
                bool desc = ((i & k) == 0);
                if (desc ? (a < c) : (a > c)) { keys[i] = c; keys[l] = a; }
            }
            __syncthreads();
        }
    }

    __shared__ float y0s[TOPK], x0s[TOPK], y1s[TOPK], x1s[TOPK], areas[TOPK];
    __shared__ int labs[TOPK];
    __shared__ int sel[TOPK];
    __shared__ unsigned char keep[TOPK];
    if (tid < TOPK) {
        u64 k = keys[tid];
        int ii = (int)(0xFFFFFFFFu - (unsigned)(k & 0xFFFFFFFFu));
        sel[tid] = ii;
        float y0 = cb[ii * 8 + 0], x0 = cb[ii * 8 + 1];
        float y1 = cb[ii * 8 + 2], x1 = cb[ii * 8 + 3];
        y0s[tid] = y0; x0s[tid] = x0; y1s[tid] = y1; x1s[tid] = x1;
        areas[tid] = (y1 - y0) * (x1 - x0);
        labs[tid] = (int)cb[ii * 8 + 6];
        keep[tid] = ((unsigned)(k >> 32) != 0u) ? 1 : 0;
    }
    __syncthreads();

    for (int j = 0; j < TOPK - 1; j++) {
        if (tid > j && tid < TOPK && keep[j] && keep[tid] && labs[tid] == labs[j]) {
            float ty0 = fmaxf(y0s[tid], y0s[j]);
            float tx0 = fmaxf(x0s[tid], x0s[j]);
            float ty1 = fminf(y1s[tid], y1s[j]);
            float tx1 = fminf(x1s[tid], x1s[j]);
            float ih = fmaxf(ty1 - ty0, 0.f);
            float iw = fmaxf(tx1 - tx0, 0.f);
            float inter = ih * iw;
            float iou = inter / (areas[tid] + areas[j] - inter + 1e-9f);
            if (iou > 0.5f) keep[tid] = 0;
        }
        __syncthreads();
    }

    if (tid < TOPK) {
        float* o = out + ((size_t)b * TOPK + tid) * 7;
        if (keep[tid]) {
            int ii = sel[tid];
            o[0] = y0s[tid]; o[1] = x0s[tid]; o[2] = y1s[tid]; o[3] = x1s[tid];
            o[4] = cb[ii * 8 + 4];
            o[5] = cb[ii * 8 + 5];
            o[6] = (float)labs[tid];
        } else {
            #pragma unroll
            for (int k = 0; k < 7; k++) o[k] = 0.f;
        }
    }
}

// ---------------- launch ----------------
static inline int ceil_div(int a, int b) { return (a + b - 1) / b; }

extern "C" void kernel_launch(void* const* d_in, const int* in_sizes, int n_in,
                              void* d_out, int out_size)
{
    (void)in_sizes; (void)n_in; (void)out_size;
    const float* images = (const float*)d_in[0];
    const float* w1 = (const float*)d_in[1];  const float* b1 = (const float*)d_in[2];
    const float* w2 = (const float*)d_in[3];  const float* b2 = (const float*)d_in[4];
    const float* w3 = (const float*)d_in[5];  const float* b3 = (const float*)d_in[6];
    const float* w4 = (const float*)d_in[7];  const float* b4 = (const float*)d_in[8];
    const float* w5 = (const float*)d_in[9];  const float* b5 = (const float*)d_in[10];
    const float* wh1 = (const float*)d_in[11]; const float* bh1 = (const float*)d_in[12];
    const float* wh2 = (const float*)d_in[13]; const float* bh2 = (const float*)d_in[14];
    float* out = (float*)d_out;

    static float *act1 = nullptr, *act2, *act3, *act4, *act5, *feat1, *feat2, *part, *cand;
    if (!act1) {
        cudaGetSymbolAddress((void**)&act1, g_act1);
        cudaGetSymbolAddress((void**)&act2, g_act2);
        cudaGetSymbolAddress((void**)&act3, g_act3);
        cudaGetSymbolAddress((void**)&act4, g_act4);
        cudaGetSymbolAddress((void**)&act5, g_act5);
        cudaGetSymbolAddress((void**)&feat1, g_feat1);
        cudaGetSymbolAddress((void**)&feat2, g_feat2);
        cudaGetSymbolAddress((void**)&part, g_part);
        cudaGetSymbolAddress((void**)&cand, g_cand);
    }

    // --- L1: 3->32, 416->208  (N = 346112, K = 27) fused from NCHW images
    gemm9f_kernel<32, 346112, 27, 1, true, true, 3, 416, 416, 208, 208>
        <<<dim3(346112 / 128, 1, 1), 128>>>(w1, images, b1, act1);

    // --- L2: 32->64, 208->104 (N = 86528, K = 288)
    gemm9f_kernel<64, 86528, 288, 1, true, false, 32, 208, 208, 104, 104>
        <<<dim3(86528 / 128, 1, 1), 128>>>(w2, act1, b2, act2);

    // --- L3: 64->128, 104->52 (N = 21632, K = 576)
    gemm9f_kernel<128, 21632, 576, 1, true, false, 64, 104, 104, 52, 52>
        <<<dim3(21632 / 128, 2, 1), 128>>>(w3, act2, b3, act3);

    // --- L4: 128->256, 52->26 (N = 5408, K = 1152), split-K 2
    gemm9f_kernel<256, 5408, 1152, 2, false, false, 128, 52, 52, 26, 26>
        <<<dim3(ceil_div(5408, 128), 4, 2), 128>>>(w4, act3, b4, part);
    reduce_kernel<256, 5408, 2, true>
        <<<ceil_div(256 * 5408 / 4, 256), 256>>>(part, b4, act4);

    // --- head2: 255 x 5408, K = 256, split-K 2
    gemm9_kernel<255, 5408, 256, 128, 128, 2, 256, false>
        <<<dim3(ceil_div(5408, 128), 2, 2), 256>>>(wh2, act4, bh2, part);
    reduce_kernel<255, 5408, 2, false>
        <<<ceil_div(255 * 5408 / 4 + 1, 256), 256>>>(part, bh2, feat2);

    // --- L5: 256->512, 26->13 (N = 1352, K = 2304), split-K 4
    gemm9f_kernel<512, 1352, 2304, 4, false, false, 256, 26, 26, 13, 13>
        <<<dim3(ceil_div(1352, 128), 8, 4), 128>>>(w5, act4, b5, part);
    reduce_kernel<512, 1352, 4, true>
        <<<ceil_div(512 * 1352 / 4, 256), 256>>>(part, b5, act5);

    // --- head1: 255 x 1352, K = 512, split-K 4
    gemm9_kernel<255, 1352, 512, 128, 128, 4, 256, false>
        <<<dim3(ceil_div(1352, 128), 2, 4), 256>>>(wh1, act5, bh1, part);
    reduce_kernel<255, 1352, 4, false>
        <<<ceil_div(255 * 1352 / 4 + 1, 256), 256>>>(part, bh1, feat1);

    // --- decode + nms
    decode_kernel<<<ceil_div(BATCH * NCAND, 256), 256>>>(feat1, feat2, cand);
    nms_kernel<<<BATCH, 512>>>(cand, out);
}